// round 9
// baseline (speedup 1.0000x reference)
#include <cuda_runtime.h>
#include <cuda_fp16.h>
#include <math.h>
#include <stdint.h>

#define BATCH   2048
#define DIM     200
#define OCH     64
#define NPIX    400          // 20x20
#define FLATK   25600        // 64*400
#define NENT    50000
#define EPSF    1e-5f

#define KTOT3   448          // scoring K': [hi(200) | lo(200) | 0(48)]
#define OKCH    7            // 448/64
#define ONTILE  256
#define ONT2    196          // ceil(50000/256)
#define NENTP   (ONT2*ONTILE)    // 50176
#define KSPLIT  8
#define KSEG    (FLATK/KSPLIT)   // 3200
#define NPADFC  256
#define FC_CHUNKS 100        // 2 passes x 50 chunks

// ---------------- scratch ----------------
__device__ float g_X[BATCH * NPIX];
__device__ float g_H[BATCH * DIM];
__device__ float g_sums[2];
__device__ float g_csum[OCH];
__device__ float g_csumsq[OCH];
__device__ float g_scale[OCH];
__device__ float g_shift[OCH];
__device__ __half g_ap[(size_t)BATCH * KTOT3];      // scoring A' 1.8MB
__device__ __half g_bp[(size_t)NENTP * KTOT3];      // scoring B' 45MB
__device__ __half g_yh[(size_t)BATCH * FLATK];      // fc A hi 105MB
__device__ __half g_yl[(size_t)BATCH * FLATK];      // fc A lo 105MB
__device__ __half g_wh[(size_t)DIM * FLATK];        // fc W hi 10.3MB
__device__ float g_hp[(size_t)KSPLIT * BATCH * NPADFC];

// ---------------- init ----------------
__global__ void k_init() {
    int t = threadIdx.x;
    if (t < 2) g_sums[t] = 0.f;
    if (t < OCH) { g_csum[t] = 0.f; g_csumsq[t] = 0.f; }
}

// ---------------- gather + chequer perm + bn0 stats ----------------
__global__ void k_gather(const float* __restrict__ nf, const float* __restrict__ rf,
                         const int* __restrict__ sub, const int* __restrict__ rel) {
    int b = blockIdx.x;
    int t = threadIdx.x;   // 512
    float v = 0.f;
    if (t < NPIX) {
        int r = t / 20, c = t % 20;
        int idx = r * 10 + (c >> 1);
        int useB = (r + c) & 1;
        v = useB ? rf[rel[b] * DIM + idx]
                 : nf[(size_t)sub[b] * DIM + idx];
        g_X[b * NPIX + t] = v;
    }
    __shared__ float ss[512], sq[512];
    ss[t] = v; sq[t] = v * v;
    __syncthreads();
    for (int s = 256; s > 0; s >>= 1) {
        if (t < s) { ss[t] += ss[t + s]; sq[t] += sq[t + s]; }
        __syncthreads();
    }
    if (t == 0) { atomicAdd(&g_sums[0], ss[0]); atomicAdd(&g_sums[1], sq[0]); }
}

// ---------------- conv prologue ----------------
__device__ __forceinline__ void conv_prologue(int b, int t, float* xs, float* fs,
                                              const float* __restrict__ fw,
                                              const int* __restrict__ rel,
                                              const float* __restrict__ bn0g,
                                              const float* __restrict__ bn0b) {
    float invN = 1.0f / (float)(BATCH * NPIX);
    float m0 = g_sums[0] * invN;
    float v0 = g_sums[1] * invN - m0 * m0;
    float sc0 = bn0g[0] * rsqrtf(v0 + EPSF);
    float sh0 = bn0b[0] - sc0 * m0;
    for (int i = t; i < 484; i += 256) {
        int ph = i / 22, pw = i % 22;
        float val = 0.f;
        if (ph >= 1 && ph <= 20 && pw >= 1 && pw <= 20)
            val = sc0 * g_X[b * NPIX + (ph - 1) * 20 + (pw - 1)] + sh0;
        xs[i] = val;
    }
    int rb = rel[b];
    for (int i = t; i < OCH * 9; i += 256) fs[i] = fw[rb * (OCH * 9) + i];
}

// ---------------- conv pass 1: channel stats ----------------
__global__ void k_conv_stats(const float* __restrict__ fw, const int* __restrict__ rel,
                             const float* __restrict__ bn0g, const float* __restrict__ bn0b) {
    int b = blockIdx.x;
    int t = threadIdx.x;
    __shared__ float xs[22 * 22];
    __shared__ float fs[OCH * 9];
    conv_prologue(b, t, xs, fs, fw, rel, bn0g, bn0b);
    __syncthreads();

    int oc = t >> 2, l4 = t & 3;
    float f[9];
#pragma unroll
    for (int j = 0; j < 9; j++) f[j] = fs[oc * 9 + j];

    float s1 = 0.f, s2 = 0.f;
#pragma unroll 4
    for (int s = 0; s < 100; s++) {
        int pix = l4 + 4 * s;
        int h = pix / 20, w = pix % 20;
        const float* xp = &xs[h * 22 + w];
        float acc = xp[0]  * f[0] + xp[1]  * f[1] + xp[2]  * f[2]
                  + xp[22] * f[3] + xp[23] * f[4] + xp[24] * f[5]
                  + xp[44] * f[6] + xp[45] * f[7] + xp[46] * f[8];
        s1 += acc; s2 += acc * acc;
    }
    s1 += __shfl_down_sync(0xffffffffu, s1, 2, 4);
    s1 += __shfl_down_sync(0xffffffffu, s1, 1, 4);
    s2 += __shfl_down_sync(0xffffffffu, s2, 2, 4);
    s2 += __shfl_down_sync(0xffffffffu, s2, 1, 4);
    if (l4 == 0) { atomicAdd(&g_csum[oc], s1); atomicAdd(&g_csumsq[oc], s2); }
}

// ---------------- compose BN2d pair ----------------
__global__ void k_chan(const float* __restrict__ cg, const float* __restrict__ cb,
                       const float* __restrict__ b1g, const float* __restrict__ b1b) {
    int t = threadIdx.x;
    if (t >= OCH) return;
    float invN = 1.0f / (float)(BATCH * NPIX);
    float m = g_csum[t] * invN;
    float v = g_csumsq[t] * invN - m * m;
    float t1 = rsqrtf(v + EPSF);
    float var1 = cg[t] * cg[t] * v * t1 * t1;
    float t2 = rsqrtf(var1 + EPSF);
    float sc = b1g[t] * cg[t] * t1 * t2;
    g_scale[t] = sc;
    g_shift[t] = b1b[t] - sc * m;
}

// ---------------- fc_w -> fp16 hi ----------------
__global__ void k_cvt_fcw(const float* __restrict__ fw) {
    int n = blockIdx.x;
    int t = threadIdx.x;
#pragma unroll 4
    for (int i = 0; i < 100; i++) {
        size_t idx = (size_t)n * FLATK + t + 256 * i;
        g_wh[idx] = __float2half_rn(fw[idx]);
    }
}

// ---------------- conv pass 2: fused BN+relu -> fp16 hi/lo ----------------
__global__ void k_conv_fused(const float* __restrict__ fw, const int* __restrict__ rel,
                             const float* __restrict__ bn0g, const float* __restrict__ bn0b) {
    int b = blockIdx.x;
    int t = threadIdx.x;
    __shared__ float xs[22 * 22];
    __shared__ float fs[OCH * 9];
    conv_prologue(b, t, xs, fs, fw, rel, bn0g, bn0b);
    __syncthreads();

    int oc = t >> 2, l4 = t & 3;
    float f[9];
#pragma unroll
    for (int j = 0; j < 9; j++) f[j] = fs[oc * 9 + j];
    float sc = g_scale[oc], sh = g_shift[oc];

    size_t base = ((size_t)b * OCH + oc) * NPIX;
#pragma unroll 4
    for (int s = 0; s < 100; s++) {
        int pix = l4 + 4 * s;
        int h = pix / 20, w = pix % 20;
        const float* xp = &xs[h * 22 + w];
        float acc = xp[0]  * f[0] + xp[1]  * f[1] + xp[2]  * f[2]
                  + xp[22] * f[3] + xp[23] * f[4] + xp[24] * f[5]
                  + xp[44] * f[6] + xp[45] * f[7] + xp[46] * f[8];
        float z = sc * acc + sh;
        z = z > 0.f ? z : 0.f;
        __half hi = __float2half_rn(z);
        g_yh[base + pix] = hi;
        g_yl[base + pix] = __float2half_rn(z - __half2float(hi));
    }
}

// ---------------- n_feats -> B' = [Bh | Bh | 0] ----------------
__global__ void k_cvt_nf(const float* __restrict__ nf) {
    int n = blockIdx.x;      // 0..NENTP-1
    int t = threadIdx.x;     // 256
    size_t base = (size_t)n * KTOT3;
    // k = t (0..255)
    {
        float x = 0.f;
        if (n < NENT && t < DIM) x = nf[(size_t)n * DIM + t];
        else if (n < NENT && t >= DIM && t < 2 * DIM) x = nf[(size_t)n * DIM + (t - DIM)];
        g_bp[base + t] = __float2half_rn(x);
    }
    // k = t + 256 (256..447)
    if (t < KTOT3 - 256) {
        int k = t + 256;
        float x = 0.f;
        if (n < NENT && k < 2 * DIM) x = nf[(size_t)n * DIM + (k - DIM)];
        g_bp[base + k] = __float2half_rn(x);
    }
}

// ---------------- mma helpers ----------------
__device__ __forceinline__ uint32_t cvta_smem(const void* p) {
    uint32_t a;
    asm("{ .reg .u64 t; cvta.to.shared.u64 t, %1; cvt.u32.u64 %0, t; }" : "=r"(a) : "l"(p));
    return a;
}
__device__ __forceinline__ void cp16(uint32_t dst, const void* src, uint32_t sz) {
    asm volatile("cp.async.cg.shared.global [%0], [%1], 16, %2;"
                 :: "r"(dst), "l"(src), "r"(sz));
}
__device__ __forceinline__ void cp_commit() {
    asm volatile("cp.async.commit_group;");
}
template <int N>
__device__ __forceinline__ void cp_wait() {
    asm volatile("cp.async.wait_group %0;" :: "n"(N));
}
__device__ __forceinline__ void ldsm_x4(uint32_t& r0, uint32_t& r1, uint32_t& r2, uint32_t& r3,
                                        uint32_t addr) {
    asm volatile("ldmatrix.sync.aligned.m8n8.x4.shared.b16 {%0,%1,%2,%3}, [%4];"
                 : "=r"(r0), "=r"(r1), "=r"(r2), "=r"(r3) : "r"(addr));
}
__device__ __forceinline__ void mma_f16(float& d0, float& d1, float& d2, float& d3,
                                        uint32_t a0, uint32_t a1, uint32_t a2, uint32_t a3,
                                        uint32_t b0, uint32_t b1) {
    asm volatile("mma.sync.aligned.m16n8k16.row.col.f32.f16.f16.f32 "
                 "{%0,%1,%2,%3}, {%4,%5,%6,%7}, {%8,%9}, {%0,%1,%2,%3};"
                 : "+f"(d0), "+f"(d1), "+f"(d2), "+f"(d3)
                 : "r"(a0), "r"(a1), "r"(a2), "r"(a3), "r"(b0), "r"(b1));
}

#define FC_STAGE 32768

// ---------------- FC GEMM: fp16 2-pass, K-split ----------------
__global__ __launch_bounds__(256, 2) void k_fc_mma() {
    extern __shared__ __align__(1024) unsigned char dsm[];
    int t = threadIdx.x;
    int lane = t & 31, wid = t >> 5;
    int wm = (wid >> 2) * 64;
    int wn = (wid & 3) * 32;
    int n0 = blockIdx.x * 128;
    int m0 = blockIdx.y * 128;
    int ks = blockIdx.z;
    size_t kbase = (size_t)ks * KSEG;

    uint32_t smemBase = cvta_smem(dsm);

    int rowL[4]; uint32_t soL[4]; int segL[4];
#pragma unroll
    for (int r = 0; r < 4; r++) {
        int e = t + 256 * r;
        rowL[r] = e >> 3;
        segL[r] = e & 7;
        soL[r] = (uint32_t)rowL[r] * 128 + (uint32_t)((segL[r] ^ (rowL[r] & 7)) << 4);
    }

    int grp = lane >> 3, li = lane & 7;
    int roffA = ((grp & 1) << 3) + li;
    int cgA = grp >> 1;
    int noffB = ((grp >> 1) << 3) + li;
    int cgB = grp & 1;

    float acc[4][4][4];
#pragma unroll
    for (int a = 0; a < 4; a++)
#pragma unroll
        for (int b = 0; b < 4; b++)
#pragma unroll
            for (int c = 0; c < 4; c++) acc[a][b][c] = 0.f;

    auto issue = [&](int idx) {
        int p = idx / 50, c = idx - p * 50;
        const __half* Ab = p ? g_yl : g_yh;
        size_t koff = kbase + (size_t)c * 64;
        uint32_t base = smemBase + (uint32_t)(idx & 1) * FC_STAGE;
#pragma unroll
        for (int r = 0; r < 4; r++) {
            size_t ga = (size_t)(m0 + rowL[r]) * FLATK + koff + segL[r] * 8;
            cp16(base + soL[r], Ab + ga, 16);
            int nrow = n0 + rowL[r];
            int ok = nrow < DIM;
            size_t gb = (size_t)(ok ? nrow : 0) * FLATK + koff + segL[r] * 8;
            cp16(base + 16384 + soL[r], g_wh + gb, ok ? 16u : 0u);
        }
        cp_commit();
    };

    issue(0);
    for (int ch = 0; ch < FC_CHUNKS; ch++) {
        if (ch < FC_CHUNKS - 1) { issue(ch + 1); cp_wait<1>(); }
        else cp_wait<0>();
        __syncthreads();
        uint32_t baseA = smemBase + (uint32_t)(ch & 1) * FC_STAGE;
        uint32_t baseB = baseA + 16384;
#pragma unroll
        for (int kf = 0; kf < 4; kf++) {
            uint32_t a[4][4];
#pragma unroll
            for (int mf = 0; mf < 4; mf++) {
                int row = wm + mf * 16 + roffA;
                uint32_t addr = baseA + (uint32_t)row * 128
                              + (uint32_t)(((kf * 2 + cgA) ^ li) << 4);
                ldsm_x4(a[mf][0], a[mf][1], a[mf][2], a[mf][3], addr);
            }
            uint32_t b[4][2];
#pragma unroll
            for (int nf2 = 0; nf2 < 2; nf2++) {
                int row = wn + nf2 * 16 + noffB;
                uint32_t addr = baseB + (uint32_t)row * 128
                              + (uint32_t)(((kf * 2 + cgB) ^ li) << 4);
                ldsm_x4(b[nf2 * 2][0], b[nf2 * 2][1], b[nf2 * 2 + 1][0], b[nf2 * 2 + 1][1], addr);
            }
#pragma unroll
            for (int mf = 0; mf < 4; mf++)
#pragma unroll
                for (int nf = 0; nf < 4; nf++)
                    mma_f16(acc[mf][nf][0], acc[mf][nf][1], acc[mf][nf][2], acc[mf][nf][3],
                            a[mf][0], a[mf][1], a[mf][2], a[mf][3],
                            b[nf][0], b[nf][1]);
        }
        __syncthreads();
    }

    int g = lane >> 2, c = lane & 3;
    float* hp = g_hp + (size_t)ks * BATCH * NPADFC;
#pragma unroll
    for (int mf = 0; mf < 4; mf++) {
#pragma unroll
        for (int nf = 0; nf < 4; nf++) {
            int n = n0 + wn + nf * 8 + c * 2;
            int m = m0 + wm + mf * 16 + g;
            float2 v0 = {acc[mf][nf][0], acc[mf][nf][1]};
            *(float2*)(hp + (size_t)m * NPADFC + n) = v0;
            float2 v1 = {acc[mf][nf][2], acc[mf][nf][3]};
            *(float2*)(hp + (size_t)(m + 8) * NPADFC + n) = v1;
        }
    }
}

// ---------------- reduce fc partials + bias ----------------
__global__ void k_fcred(const float* __restrict__ fb) {
    int m = blockIdx.x;
    int t = threadIdx.x;
    if (t >= DIM) return;
    float s = fb[t];
#pragma unroll
    for (int z = 0; z < KSPLIT; z++)
        s += g_hp[((size_t)z * BATCH + m) * NPADFC + t];
    g_H[m * DIM + t] = s;
}

// ---------------- bn1d + relu -> A' = [hi(200) | lo(200) | 0] ----------------
__global__ void k_bn1d(const float* __restrict__ b2g, const float* __restrict__ b2b) {
    int d = blockIdx.x;     // 0..447
    int t = threadIdx.x;    // 256
    if (d >= 2 * DIM) {     // zero-fill tail columns
        __half z16 = __float2half_rn(0.f);
        for (int i = t; i < BATCH; i += 256)
            g_ap[(size_t)i * KTOT3 + d] = z16;
        return;
    }
    if (d >= DIM) return;   // lo written by block d-200's owner
    float vals[8];
    float s1 = 0.f, s2 = 0.f;
#pragma unroll
    for (int i = 0; i < 8; i++) {
        float h = g_H[(t + 256 * i) * DIM + d];
        vals[i] = h; s1 += h; s2 += h * h;
    }
    __shared__ float ss[256], sq[256];
    ss[t] = s1; sq[t] = s2;
    __syncthreads();
    for (int s = 128; s > 0; s >>= 1) {
        if (t < s) { ss[t] += ss[t + s]; sq[t] += sq[t + s]; }
        __syncthreads();
    }
    __shared__ float ssc, ssh;
    if (t == 0) {
        float m = ss[0] / (float)BATCH;
        float v = sq[0] / (float)BATCH - m * m;
        float sc = b2g[d] * rsqrtf(v + EPSF);
        ssc = sc; ssh = b2b[d] - sc * m;
    }
    __syncthreads();
    float sc = ssc, sh = ssh;
#pragma unroll
    for (int i = 0; i < 8; i++) {
        float z = sc * vals[i] + sh;
        z = z > 0.f ? z : 0.f;
        __half hi = __float2half_rn(z);
        size_t base = (size_t)(t + 256 * i) * KTOT3;
        g_ap[base + d] = hi;
        g_ap[base + DIM + d] = __float2half_rn(z - __half2float(hi));
    }
}

// ---------------- scoring GEMM: CTA 128x256, warp 64x64, 3-stage ----------------
#define OUT_ASZ 16384
#define OUT_BSZ 32768
#define OUT_STAGE (OUT_ASZ + OUT_BSZ)   // 48KB

__global__ __launch_bounds__(256, 1) void k_out_mma(const float* __restrict__ eb,
                                                    float* __restrict__ out) {
    extern __shared__ __align__(1024) unsigned char dsm[];
    int t = threadIdx.x;
    int lane = t & 31, wid = t >> 5;
    int wm = (wid >> 2) * 64;        // 0 / 64
    int wn = (wid & 3) * 64;         // 0..192
    int m0 = blockIdx.x * 128;
    int n0 = blockIdx.y * ONTILE;

    uint32_t smemBase = cvta_smem(dsm);

    // A load geometry: 1024 16B units (4/thread); B: 2048 (8/thread)
    int rowA[4]; uint32_t soA[4]; int segA[4];
#pragma unroll
    for (int r = 0; r < 4; r++) {
        int e = t + 256 * r;
        rowA[r] = e >> 3; segA[r] = e & 7;
        soA[r] = (uint32_t)rowA[r] * 128 + (uint32_t)((segA[r] ^ (rowA[r] & 7)) << 4);
    }
    int rowB[8]; uint32_t soB[8]; int segB[8];
#pragma unroll
    for (int r = 0; r < 8; r++) {
        int e = t + 256 * r;
        rowB[r] = e >> 3; segB[r] = e & 7;
        soB[r] = (uint32_t)rowB[r] * 128 + (uint32_t)((segB[r] ^ (rowB[r] & 7)) << 4);
    }
    const __half* pA = g_ap + (size_t)m0 * KTOT3;
    const __half* pB = g_bp + (size_t)n0 * KTOT3;

    int grp = lane >> 3, li = lane & 7;
    int roffA = ((grp & 1) << 3) + li;
    int cgA = grp >> 1;
    int noffB = ((grp >> 1) << 3) + li;
    int cgB = grp & 1;

    float acc[4][8][4];
#pragma unroll
    for (int a = 0; a < 4; a++)
#pragma unroll
        for (int b = 0; b < 8; b++)
#pragma unroll
            for (int c = 0; c < 4; c++) acc[a][b][c] = 0.f;

    auto issue = [&](int ch) {
        uint32_t base = smemBase + (uint32_t)(ch % 3) * OUT_STAGE;
#pragma unroll
        for (int r = 0; r < 4; r++) {
            size_t ga = (size_t)rowA[r] * KTOT3 + ch * 64 + segA[r] * 8;
            cp16(base + soA[r], pA + ga, 16);
        }
#pragma unroll
        for (int r = 0; r < 8; r++) {
            size_t gb = (size_t)rowB[r] * KTOT3 + ch * 64 + segB[r] * 8;
            cp16(base + OUT_ASZ + soB[r], pB + gb, 16);
        }
        cp_commit();
    };

    issue(0); issue(1);
    for (int ch = 0; ch < OKCH; ch++) {
        if (ch + 2 < OKCH) { issue(ch + 2); cp_wait<2>(); }
        else if (ch + 1 < OKCH) cp_wait<1>();
        else cp_wait<0>();
        __syncthreads();
        uint32_t baseA = smemBase + (uint32_t)(ch % 3) * OUT_STAGE;
        uint32_t baseB = baseA + OUT_ASZ;
#pragma unroll
        for (int kf = 0; kf < 4; kf++) {
            uint32_t a[4][4];
#pragma unroll
            for (int mf = 0; mf < 4; mf++) {
                int row = wm + mf * 16 + roffA;
                uint32_t addr = baseA + (uint32_t)row * 128
                              + (uint32_t)(((kf * 2 + cgA) ^ li) << 4);
                ldsm_x4(a[mf][0], a[mf][1], a[mf][2], a[mf][3], addr);
            }
            uint32_t b[8][2];
#pragma unroll
            for (int nf2 = 0; nf2 < 4; nf2++) {
                int row = wn + nf2 * 16 + noffB;
                uint32_t addr = baseB + (uint32_t)row * 128
                              + (uint32_t)(((kf * 2 + cgB) ^ li) << 4);
                ldsm_x4(b[nf2 * 2][0], b[nf2 * 2][1], b[nf2 * 2 + 1][0], b[nf2 * 2 + 1][1], addr);
            }
#pragma unroll
            for (int mf = 0; mf < 4; mf++)
#pragma unroll
                for (int nf = 0; nf < 8; nf++)
                    mma_f16(acc[mf][nf][0], acc[mf][nf][1], acc[mf][nf][2], acc[mf][nf][3],
                            a[mf][0], a[mf][1], a[mf][2], a[mf][3],
                            b[nf][0], b[nf][1]);
        }
        __syncthreads();
    }

    int g = lane >> 2, c = lane & 3;
#pragma unroll
    for (int mf = 0; mf < 4; mf++) {
#pragma unroll
        for (int nf = 0; nf < 8; nf++) {
            int n = n0 + wn + nf * 8 + c * 2;
            if (n < NENT) {
                float2 bias = *(const float2*)(eb + n);
                int m = m0 + wm + mf * 16 + g;
                float2 v0 = {acc[mf][nf][0] + bias.x, acc[mf][nf][1] + bias.y};
                *(float2*)(out + (size_t)m * NENT + n) = v0;
                float2 v1 = {acc[mf][nf][2] + bias.x, acc[mf][nf][3] + bias.y};
                *(float2*)(out + (size_t)(m + 8) * NENT + n) = v1;
            }
        }
    }
}

// ---------------- launch ----------------
extern "C" void kernel_launch(void* const* d_in, const int* in_sizes, int n_in,
                              void* d_out, int out_size) {
    const float* nf   = (const float*)d_in[0];
    const float* rf   = (const float*)d_in[1];
    const float* fw   = (const float*)d_in[2];
    const float* bn0g = (const float*)d_in[3];
    const float* bn0b = (const float*)d_in[4];
    const float* cbng = (const float*)d_in[5];
    const float* cbnb = (const float*)d_in[6];
    const float* bn1g = (const float*)d_in[7];
    const float* bn1b = (const float*)d_in[8];
    const float* fcw  = (const float*)d_in[9];
    const float* fcb  = (const float*)d_in[10];
    const float* bn2g = (const float*)d_in[11];
    const float* bn2b = (const float*)d_in[12];
    const float* eb   = (const float*)d_in[13];
    const int*   sub  = (const int*)d_in[14];
    const int*   rel  = (const int*)d_in[15];
    float* out = (float*)d_out;

    cudaFuncSetAttribute(k_out_mma, cudaFuncAttributeMaxDynamicSharedMemorySize, 3 * OUT_STAGE);
    cudaFuncSetAttribute(k_fc_mma, cudaFuncAttributeMaxDynamicSharedMemorySize, 2 * FC_STAGE);

    k_init<<<1, 256>>>();
    k_gather<<<BATCH, 512>>>(nf, rf, sub, rel);
    k_conv_stats<<<BATCH, 256>>>(fw, rel, bn0g, bn0b);
    k_chan<<<1, 64>>>(cbng, cbnb, bn1g, bn1b);
    k_cvt_fcw<<<DIM, 256>>>(fcw);
    k_conv_fused<<<BATCH, 256>>>(fw, rel, bn0g, bn0b);
    k_cvt_nf<<<NENTP, 256>>>(nf);
    k_fc_mma<<<dim3(2, 16, KSPLIT), 256, 2 * FC_STAGE>>>();
    k_fcred<<<BATCH, 256>>>(fcb);
    k_bn1d<<<KTOT3, 256>>>(bn2g, bn2b);
    k_out_mma<<<dim3(16, ONT2), 256, 3 * OUT_STAGE>>>(eb, out);
}

// round 10
// speedup vs baseline: 1.0478x; 1.0478x over previous
#include <cuda_runtime.h>
#include <cuda_fp16.h>
#include <math.h>
#include <stdint.h>

#define BATCH   2048
#define DIM     200
#define OCH     64
#define NPIX    400          // 20x20
#define FLATK   25600        // 64*400
#define NENT    50000
#define EPSF    1e-5f

#define KPASS   256          // padded K per pass (200 -> 256)
#define KTOT2   512          // scoring A': [Ah | Al]
#define NTILE   128
#define NTILES  391
#define NENTP   (NTILES*NTILE)   // 50048
#define KSPLIT  8
#define KSEG    (FLATK/KSPLIT)   // 3200
#define NPADFC  256
#define FC_CHUNKS 100        // 2 passes x 50 chunks

// ---------------- scratch ----------------
__device__ float g_X[BATCH * NPIX];
__device__ float g_H[BATCH * DIM];
__device__ float g_sums[2];
__device__ float g_csum[OCH];
__device__ float g_csumsq[OCH];
__device__ float g_scale[OCH];
__device__ float g_shift[OCH];
__device__ __half g_ap[(size_t)BATCH * KTOT2];      // scoring A' [Ah|Al] 2MB
__device__ __half g_bp[(size_t)NENTP * KPASS];      // scoring B (hi only) 25.6MB
__device__ __half g_yh[(size_t)BATCH * FLATK];      // fc A hi 105MB
__device__ __half g_yl[(size_t)BATCH * FLATK];      // fc A lo 105MB
__device__ __half g_wh[(size_t)DIM * FLATK];        // fc W hi 10.3MB
__device__ float g_hp[(size_t)KSPLIT * BATCH * NPADFC];

// ---------------- init ----------------
__global__ void k_init() {
    int t = threadIdx.x;
    if (t < 2) g_sums[t] = 0.f;
    if (t < OCH) { g_csum[t] = 0.f; g_csumsq[t] = 0.f; }
}

// ---------------- gather + chequer perm + bn0 stats ----------------
__global__ void k_gather(const float* __restrict__ nf, const float* __restrict__ rf,
                         const int* __restrict__ sub, const int* __restrict__ rel) {
    int b = blockIdx.x;
    int t = threadIdx.x;   // 512
    float v = 0.f;
    if (t < NPIX) {
        int r = t / 20, c = t % 20;
        int idx = r * 10 + (c >> 1);
        int useB = (r + c) & 1;
        v = useB ? rf[rel[b] * DIM + idx]
                 : nf[(size_t)sub[b] * DIM + idx];
        g_X[b * NPIX + t] = v;
    }
    __shared__ float ss[512], sq[512];
    ss[t] = v; sq[t] = v * v;
    __syncthreads();
    for (int s = 256; s > 0; s >>= 1) {
        if (t < s) { ss[t] += ss[t + s]; sq[t] += sq[t + s]; }
        __syncthreads();
    }
    if (t == 0) { atomicAdd(&g_sums[0], ss[0]); atomicAdd(&g_sums[1], sq[0]); }
}

// ---------------- conv prologue ----------------
__device__ __forceinline__ void conv_prologue(int b, int t, float* xs, float* fs,
                                              const float* __restrict__ fw,
                                              const int* __restrict__ rel,
                                              const float* __restrict__ bn0g,
                                              const float* __restrict__ bn0b) {
    float invN = 1.0f / (float)(BATCH * NPIX);
    float m0 = g_sums[0] * invN;
    float v0 = g_sums[1] * invN - m0 * m0;
    float sc0 = bn0g[0] * rsqrtf(v0 + EPSF);
    float sh0 = bn0b[0] - sc0 * m0;
    for (int i = t; i < 484; i += 256) {
        int ph = i / 22, pw = i % 22;
        float val = 0.f;
        if (ph >= 1 && ph <= 20 && pw >= 1 && pw <= 20)
            val = sc0 * g_X[b * NPIX + (ph - 1) * 20 + (pw - 1)] + sh0;
        xs[i] = val;
    }
    int rb = rel[b];
    for (int i = t; i < OCH * 9; i += 256) fs[i] = fw[rb * (OCH * 9) + i];
}

// ---------------- conv pass 1: channel stats ----------------
__global__ void k_conv_stats(const float* __restrict__ fw, const int* __restrict__ rel,
                             const float* __restrict__ bn0g, const float* __restrict__ bn0b) {
    int b = blockIdx.x;
    int t = threadIdx.x;
    __shared__ float xs[22 * 22];
    __shared__ float fs[OCH * 9];
    conv_prologue(b, t, xs, fs, fw, rel, bn0g, bn0b);
    __syncthreads();

    int oc = t >> 2, l4 = t & 3;
    float f[9];
#pragma unroll
    for (int j = 0; j < 9; j++) f[j] = fs[oc * 9 + j];

    float s1 = 0.f, s2 = 0.f;
#pragma unroll 4
    for (int s = 0; s < 100; s++) {
        int pix = l4 + 4 * s;
        int h = pix / 20, w = pix % 20;
        const float* xp = &xs[h * 22 + w];
        float acc = xp[0]  * f[0] + xp[1]  * f[1] + xp[2]  * f[2]
                  + xp[22] * f[3] + xp[23] * f[4] + xp[24] * f[5]
                  + xp[44] * f[6] + xp[45] * f[7] + xp[46] * f[8];
        s1 += acc; s2 += acc * acc;
    }
    s1 += __shfl_down_sync(0xffffffffu, s1, 2, 4);
    s1 += __shfl_down_sync(0xffffffffu, s1, 1, 4);
    s2 += __shfl_down_sync(0xffffffffu, s2, 2, 4);
    s2 += __shfl_down_sync(0xffffffffu, s2, 1, 4);
    if (l4 == 0) { atomicAdd(&g_csum[oc], s1); atomicAdd(&g_csumsq[oc], s2); }
}

// ---------------- compose BN2d pair ----------------
__global__ void k_chan(const float* __restrict__ cg, const float* __restrict__ cb,
                       const float* __restrict__ b1g, const float* __restrict__ b1b) {
    int t = threadIdx.x;
    if (t >= OCH) return;
    float invN = 1.0f / (float)(BATCH * NPIX);
    float m = g_csum[t] * invN;
    float v = g_csumsq[t] * invN - m * m;
    float t1 = rsqrtf(v + EPSF);
    float var1 = cg[t] * cg[t] * v * t1 * t1;
    float t2 = rsqrtf(var1 + EPSF);
    float sc = b1g[t] * cg[t] * t1 * t2;
    g_scale[t] = sc;
    g_shift[t] = b1b[t] - sc * m;
}

// ---------------- fc_w -> fp16 hi ----------------
__global__ void k_cvt_fcw(const float* __restrict__ fw) {
    int n = blockIdx.x;
    int t = threadIdx.x;
#pragma unroll 4
    for (int i = 0; i < 100; i++) {
        size_t idx = (size_t)n * FLATK + t + 256 * i;
        g_wh[idx] = __float2half_rn(fw[idx]);
    }
}

// ---------------- conv pass 2: fused BN+relu -> fp16 hi/lo ----------------
__global__ void k_conv_fused(const float* __restrict__ fw, const int* __restrict__ rel,
                             const float* __restrict__ bn0g, const float* __restrict__ bn0b) {
    int b = blockIdx.x;
    int t = threadIdx.x;
    __shared__ float xs[22 * 22];
    __shared__ float fs[OCH * 9];
    conv_prologue(b, t, xs, fs, fw, rel, bn0g, bn0b);
    __syncthreads();

    int oc = t >> 2, l4 = t & 3;
    float f[9];
#pragma unroll
    for (int j = 0; j < 9; j++) f[j] = fs[oc * 9 + j];
    float sc = g_scale[oc], sh = g_shift[oc];

    size_t base = ((size_t)b * OCH + oc) * NPIX;
#pragma unroll 4
    for (int s = 0; s < 100; s++) {
        int pix = l4 + 4 * s;
        int h = pix / 20, w = pix % 20;
        const float* xp = &xs[h * 22 + w];
        float acc = xp[0]  * f[0] + xp[1]  * f[1] + xp[2]  * f[2]
                  + xp[22] * f[3] + xp[23] * f[4] + xp[24] * f[5]
                  + xp[44] * f[6] + xp[45] * f[7] + xp[46] * f[8];
        float z = sc * acc + sh;
        z = z > 0.f ? z : 0.f;
        __half hi = __float2half_rn(z);
        g_yh[base + pix] = hi;
        g_yl[base + pix] = __float2half_rn(z - __half2float(hi));
    }
}

// ---------------- n_feats -> fp16 hi (padded) ----------------
__global__ void k_cvt_nf(const float* __restrict__ nf) {
    int n = blockIdx.x;      // 0..NENTP-1
    int k = threadIdx.x;     // 0..255
    float x = 0.f;
    if (n < NENT && k < DIM) x = nf[(size_t)n * DIM + k];
    g_bp[(size_t)n * KPASS + k] = __float2half_rn(x);
}

// ---------------- mma helpers ----------------
__device__ __forceinline__ uint32_t cvta_smem(const void* p) {
    uint32_t a;
    asm("{ .reg .u64 t; cvta.to.shared.u64 t, %1; cvt.u32.u64 %0, t; }" : "=r"(a) : "l"(p));
    return a;
}
__device__ __forceinline__ void cp16(uint32_t dst, const void* src, uint32_t sz) {
    asm volatile("cp.async.cg.shared.global [%0], [%1], 16, %2;"
                 :: "r"(dst), "l"(src), "r"(sz));
}
__device__ __forceinline__ void cp_commit() {
    asm volatile("cp.async.commit_group;");
}
template <int N>
__device__ __forceinline__ void cp_wait() {
    asm volatile("cp.async.wait_group %0;" :: "n"(N));
}
__device__ __forceinline__ void ldsm_x4(uint32_t& r0, uint32_t& r1, uint32_t& r2, uint32_t& r3,
                                        uint32_t addr) {
    asm volatile("ldmatrix.sync.aligned.m8n8.x4.shared.b16 {%0,%1,%2,%3}, [%4];"
                 : "=r"(r0), "=r"(r1), "=r"(r2), "=r"(r3) : "r"(addr));
}
__device__ __forceinline__ void mma_f16(float& d0, float& d1, float& d2, float& d3,
                                        uint32_t a0, uint32_t a1, uint32_t a2, uint32_t a3,
                                        uint32_t b0, uint32_t b1) {
    asm volatile("mma.sync.aligned.m16n8k16.row.col.f32.f16.f16.f32 "
                 "{%0,%1,%2,%3}, {%4,%5,%6,%7}, {%8,%9}, {%0,%1,%2,%3};"
                 : "+f"(d0), "+f"(d1), "+f"(d2), "+f"(d3)
                 : "r"(a0), "r"(a1), "r"(a2), "r"(a3), "r"(b0), "r"(b1));
}

// ---------------- FC GEMM: CTA 128Mx256N, 512 threads, single N-tile ----------------
#define FC_ASZ 16384
#define FC_BSZ 32768
#define FC_STG (FC_ASZ + FC_BSZ)    // 48KB per stage

__global__ __launch_bounds__(512, 1) void k_fc_mma() {
    extern __shared__ __align__(1024) unsigned char dsm[];
    int t = threadIdx.x;
    int lane = t & 31, wid = t >> 5;     // 16 warps
    int wm = (wid >> 3) * 64;            // 0 / 64
    int wn = (wid & 7) * 32;             // 0..224
    int m0 = blockIdx.y * 128;
    int ks = blockIdx.z;
    size_t kbase = (size_t)ks * KSEG;

    uint32_t smemBase = cvta_smem(dsm);

    // A: 1024 16B units / 512 threads = 2 each; B: 2048 / 512 = 4 each
    int rowA[2]; uint32_t soA[2]; int segA[2];
#pragma unroll
    for (int r = 0; r < 2; r++) {
        int e = t + 512 * r;
        rowA[r] = e >> 3; segA[r] = e & 7;
        soA[r] = (uint32_t)rowA[r] * 128 + (uint32_t)((segA[r] ^ (rowA[r] & 7)) << 4);
    }
    int rowB[4]; uint32_t soB[4]; int segB[4];
#pragma unroll
    for (int r = 0; r < 4; r++) {
        int e = t + 512 * r;
        rowB[r] = e >> 3; segB[r] = e & 7;
        soB[r] = (uint32_t)rowB[r] * 128 + (uint32_t)((segB[r] ^ (rowB[r] & 7)) << 4);
    }

    int grp = lane >> 3, li = lane & 7;
    int roffA = ((grp & 1) << 3) + li;
    int cgA = grp >> 1;
    int noffB = ((grp >> 1) << 3) + li;
    int cgB = grp & 1;

    float acc[4][4][4];
#pragma unroll
    for (int a = 0; a < 4; a++)
#pragma unroll
        for (int b = 0; b < 4; b++)
#pragma unroll
            for (int c = 0; c < 4; c++) acc[a][b][c] = 0.f;

    auto issue = [&](int idx) {
        int p = idx / 50, c = idx - p * 50;
        const __half* Ab = p ? g_yl : g_yh;
        size_t koff = kbase + (size_t)c * 64;
        uint32_t base = smemBase + (uint32_t)(idx & 1) * FC_STG;
#pragma unroll
        for (int r = 0; r < 2; r++) {
            size_t ga = (size_t)(m0 + rowA[r]) * FLATK + koff + segA[r] * 8;
            cp16(base + soA[r], Ab + ga, 16);
        }
#pragma unroll
        for (int r = 0; r < 4; r++) {
            int nrow = rowB[r];
            int ok = nrow < DIM;
            size_t gb = (size_t)(ok ? nrow : 0) * FLATK + koff + segB[r] * 8;
            cp16(base + FC_ASZ + soB[r], g_wh + gb, ok ? 16u : 0u);
        }
        cp_commit();
    };

    issue(0);
    for (int ch = 0; ch < FC_CHUNKS; ch++) {
        if (ch < FC_CHUNKS - 1) { issue(ch + 1); cp_wait<1>(); }
        else cp_wait<0>();
        __syncthreads();
        uint32_t baseA = smemBase + (uint32_t)(ch & 1) * FC_STG;
        uint32_t baseB = baseA + FC_ASZ;
#pragma unroll
        for (int kf = 0; kf < 4; kf++) {
            uint32_t a[4][4];
#pragma unroll
            for (int mf = 0; mf < 4; mf++) {
                int row = wm + mf * 16 + roffA;
                uint32_t addr = baseA + (uint32_t)row * 128
                              + (uint32_t)(((kf * 2 + cgA) ^ li) << 4);
                ldsm_x4(a[mf][0], a[mf][1], a[mf][2], a[mf][3], addr);
            }
            uint32_t b[4][2];
#pragma unroll
            for (int nf2 = 0; nf2 < 2; nf2++) {
                int row = wn + nf2 * 16 + noffB;
                uint32_t addr = baseB + (uint32_t)row * 128
                              + (uint32_t)(((kf * 2 + cgB) ^ li) << 4);
                ldsm_x4(b[nf2 * 2][0], b[nf2 * 2][1], b[nf2 * 2 + 1][0], b[nf2 * 2 + 1][1], addr);
            }
#pragma unroll
            for (int mf = 0; mf < 4; mf++)
#pragma unroll
                for (int nf = 0; nf < 4; nf++)
                    mma_f16(acc[mf][nf][0], acc[mf][nf][1], acc[mf][nf][2], acc[mf][nf][3],
                            a[mf][0], a[mf][1], a[mf][2], a[mf][3],
                            b[nf][0], b[nf][1]);
        }
        __syncthreads();
    }

    int g = lane >> 2, c = lane & 3;
    float* hp = g_hp + (size_t)ks * BATCH * NPADFC;
#pragma unroll
    for (int mf = 0; mf < 4; mf++) {
#pragma unroll
        for (int nf = 0; nf < 4; nf++) {
            int n = wn + nf * 8 + c * 2;
            int m = m0 + wm + mf * 16 + g;
            float2 v0 = {acc[mf][nf][0], acc[mf][nf][1]};
            *(float2*)(hp + (size_t)m * NPADFC + n) = v0;
            float2 v1 = {acc[mf][nf][2], acc[mf][nf][3]};
            *(float2*)(hp + (size_t)(m + 8) * NPADFC + n) = v1;
        }
    }
}

// ---------------- reduce fc partials + bias ----------------
__global__ void k_fcred(const float* __restrict__ fb) {
    int m = blockIdx.x;
    int t = threadIdx.x;
    if (t >= DIM) return;
    float s = fb[t];
#pragma unroll
    for (int z = 0; z < KSPLIT; z++)
        s += g_hp[((size_t)z * BATCH + m) * NPADFC + t];
    g_H[m * DIM + t] = s;
}

// ---------------- bn1d + relu -> A' = [Ah | Al] fp16 ----------------
__global__ void k_bn1d(const float* __restrict__ b2g, const float* __restrict__ b2b) {
    int d = blockIdx.x;     // 0..255
    int t = threadIdx.x;    // 256
    __half z16 = __float2half_rn(0.f);
    if (d >= DIM) {
        for (int i = t; i < BATCH; i += 256) {
            size_t base = (size_t)i * KTOT2 + d;
            g_ap[base] = z16; g_ap[base + KPASS] = z16;
        }
        return;
    }
    float vals[8];
    float s1 = 0.f, s2 = 0.f;
#pragma unroll
    for (int i = 0; i < 8; i++) {
        float h = g_H[(t + 256 * i) * DIM + d];
        vals[i] = h; s1 += h; s2 += h * h;
    }
    __shared__ float ss[256], sq[256];
    ss[t] = s1; sq[t] = s2;
    __syncthreads();
    for (int s = 128; s > 0; s >>= 1) {
        if (t < s) { ss[t] += ss[t + s]; sq[t] += sq[t + s]; }
        __syncthreads();
    }
    __shared__ float ssc, ssh;
    if (t == 0) {
        float m = ss[0] / (float)BATCH;
        float v = sq[0] / (float)BATCH - m * m;
        float sc = b2g[d] * rsqrtf(v + EPSF);
        ssc = sc; ssh = b2b[d] - sc * m;
    }
    __syncthreads();
    float sc = ssc, sh = ssh;
#pragma unroll
    for (int i = 0; i < 8; i++) {
        float z = sc * vals[i] + sh;
        z = z > 0.f ? z : 0.f;
        __half hi = __float2half_rn(z);
        size_t base = (size_t)(t + 256 * i) * KTOT2 + d;
        g_ap[base] = hi;
        g_ap[base + KPASS] = __float2half_rn(z - __half2float(hi));
    }
}

// ---------------- scoring GEMM: fp16 2-pass, K'=512 (R8 proven config) ----------------
#define STAGE_BYTES 32768

__global__ __launch_bounds__(256, 2) void k_out_mma(const float* __restrict__ eb,
                                                    float* __restrict__ out) {
    extern __shared__ __align__(1024) unsigned char dsm[];
    int t = threadIdx.x;
    int lane = t & 31, wid = t >> 5;
    int wm = (wid >> 2) * 64;
    int wn = (wid & 3) * 32;
    int m0 = blockIdx.x * 128;
    int n0 = blockIdx.y * NTILE;

    uint32_t smemBase = cvta_smem(dsm);

    int rowL[4]; uint32_t soL[4]; int segL[4];
#pragma unroll
    for (int r = 0; r < 4; r++) {
        int e = t + 256 * r;
        rowL[r] = e >> 3;
        segL[r] = e & 7;
        soL[r] = (uint32_t)rowL[r] * 128 + (uint32_t)((segL[r] ^ (rowL[r] & 7)) << 4);
    }
    const __half* pA = g_ap + (size_t)m0 * KTOT2;
    const __half* pB = g_bp + (size_t)n0 * KPASS;

    int grp = lane >> 3, li = lane & 7;
    int roffA = ((grp & 1) << 3) + li;
    int cgA = grp >> 1;
    int noffB = ((grp >> 1) << 3) + li;
    int cgB = grp & 1;

    float acc[4][4][4];
#pragma unroll
    for (int a = 0; a < 4; a++)
#pragma unroll
        for (int b = 0; b < 4; b++)
#pragma unroll
            for (int c = 0; c < 4; c++) acc[a][b][c] = 0.f;

    auto issue = [&](int ch) {
        uint32_t base = smemBase + (uint32_t)(ch & 1) * STAGE_BYTES;
        int cb = ch & 3;   // B repeats over the two passes
#pragma unroll
        for (int r = 0; r < 4; r++) {
            size_t ga = (size_t)rowL[r] * KTOT2 + ch * 64 + segL[r] * 8;
            cp16(base + soL[r], pA + ga, 16);
            size_t gb = (size_t)rowL[r] * KPASS + cb * 64 + segL[r] * 8;
            cp16(base + 16384 + soL[r], pB + gb, 16);
        }
        cp_commit();
    };

    issue(0);
    for (int ch = 0; ch < 8; ch++) {
        if (ch < 7) { issue(ch + 1); cp_wait<1>(); }
        else cp_wait<0>();
        __syncthreads();
        uint32_t baseA = smemBase + (uint32_t)(ch & 1) * STAGE_BYTES;
        uint32_t baseB = baseA + 16384;
#pragma unroll
        for (int kf = 0; kf < 4; kf++) {
            uint32_t a[4][4];
#pragma unroll
            for (int mf = 0; mf < 4; mf++) {
                int row = wm + mf * 16 + roffA;
                uint32_t addr = baseA + (uint32_t)row * 128
                              + (uint32_t)(((kf * 2 + cgA) ^ li) << 4);
                ldsm_x4(a[mf][0], a[mf][1], a[mf][2], a[mf][3], addr);
            }
            uint32_t b[4][2];
#pragma unroll
            for (int nf2 = 0; nf2 < 2; nf2++) {
                int row = wn + nf2 * 16 + noffB;
                uint32_t addr = baseB + (uint32_t)row * 128
                              + (uint32_t)(((kf * 2 + cgB) ^ li) << 4);
                ldsm_x4(b[nf2 * 2][0], b[nf2 * 2][1], b[nf2 * 2 + 1][0], b[nf2 * 2 + 1][1], addr);
            }
#pragma unroll
            for (int mf = 0; mf < 4; mf++)
#pragma unroll
                for (int nf = 0; nf < 4; nf++)
                    mma_f16(acc[mf][nf][0], acc[mf][nf][1], acc[mf][nf][2], acc[mf][nf][3],
                            a[mf][0], a[mf][1], a[mf][2], a[mf][3],
                            b[nf][0], b[nf][1]);
        }
        __syncthreads();
    }

    int g = lane >> 2, c = lane & 3;
#pragma unroll
    for (int mf = 0; mf < 4; mf++) {
#pragma unroll
        for (int nf = 0; nf < 4; nf++) {
            int n = n0 + wn + nf * 8 + c * 2;
            if (n < NENT) {
                float2 bias = *(const float2*)(eb + n);
                int m = m0 + wm + mf * 16 + g;
                float2 v0 = {acc[mf][nf][0] + bias.x, acc[mf][nf][1] + bias.y};
                *(float2*)(out + (size_t)m * NENT + n) = v0;
                float2 v1 = {acc[mf][nf][2] + bias.x, acc[mf][nf][3] + bias.y};
                *(float2*)(out + (size_t)(m + 8) * NENT + n) = v1;
            }
        }
    }
}

// ---------------- launch ----------------
extern "C" void kernel_launch(void* const* d_in, const int* in_sizes, int n_in,
                              void* d_out, int out_size) {
    const float* nf   = (const float*)d_in[0];
    const float* rf   = (const float*)d_in[1];
    const float* fw   = (const float*)d_in[2];
    const float* bn0g = (const float*)d_in[3];
    const float* bn0b = (const float*)d_in[4];
    const float* cbng = (const float*)d_in[5];
    const float* cbnb = (const float*)d_in[6];
    const float* bn1g = (const float*)d_in[7];
    const float* bn1b = (const float*)d_in[8];
    const float* fcw  = (const float*)d_in[9];
    const float* fcb  = (const float*)d_in[10];
    const float* bn2g = (const float*)d_in[11];
    const float* bn2b = (const float*)d_in[12];
    const float* eb   = (const float*)d_in[13];
    const int*   sub  = (const int*)d_in[14];
    const int*   rel  = (const int*)d_in[15];
    float* out = (float*)d_out;

    cudaFuncSetAttribute(k_out_mma, cudaFuncAttributeMaxDynamicSharedMemorySize, 2 * STAGE_BYTES);
    cudaFuncSetAttribute(k_fc_mma, cudaFuncAttributeMaxDynamicSharedMemorySize, 2 * FC_STG);

    k_init<<<1, 256>>>();
    k_gather<<<BATCH, 512>>>(nf, rf, sub, rel);
    k_conv_stats<<<BATCH, 256>>>(fw, rel, bn0g, bn0b);
    k_chan<<<1, 64>>>(cbng, cbnb, bn1g, bn1b);
    k_cvt_fcw<<<DIM, 256>>>(fcw);
    k_conv_fused<<<BATCH, 256>>>(fw, rel, bn0g, bn0b);
    k_cvt_nf<<<NENTP, 256>>>(nf);
    k_fc_mma<<<dim3(1, 16, KSPLIT), 512, 2 * FC_STG>>>();
    k_fcred<<<BATCH, 256>>>(fcb);
    k_bn1d<<<KPASS, 256>>>(bn2g, bn2b);
    k_out_mma<<<dim3(16, NTILES), 256, 2 * STAGE_BYTES>>>(eb, out);
}

// round 11
// speedup vs baseline: 1.1139x; 1.0631x over previous
#include <cuda_runtime.h>
#include <cuda_fp16.h>
#include <math.h>
#include <stdint.h>

#define BATCH   2048
#define DIM     200
#define OCH     64
#define NPIX    400          // 20x20
#define FLATK   25600        // 64*400
#define NENT    50000
#define EPSF    1e-5f

#define KPASS   256          // padded K per pass (200 -> 256)
#define KTOT2   512          // scoring A': [Ah | Al]
#define NTILE   128
#define NTILES  391
#define NENTP   (NTILES*NTILE)   // 50048
#define KSPLIT  8
#define KSEG    (FLATK/KSPLIT)   // 3200
#define NPADFC  256
#define FC_CHUNKS 100        // 2 passes x 50 chunks

// ---------------- scratch ----------------
__device__ float g_X[BATCH * NPIX];
__device__ float g_H[BATCH * DIM];
__device__ float g_sums[2];
__device__ float g_csum[OCH];
__device__ float g_csumsq[OCH];
__device__ float g_scale[OCH];
__device__ float g_shift[OCH];
__device__ __half g_ap[(size_t)BATCH * KTOT2];      // scoring A' [Ah|Al] 2MB
__device__ __half g_bp[(size_t)NENTP * KPASS];      // scoring B (hi only) 25.6MB
__device__ __half g_yh[(size_t)BATCH * FLATK];      // fc A hi 105MB
__device__ __half g_yl[(size_t)BATCH * FLATK];      // fc A lo 105MB
__device__ __half g_wh[(size_t)DIM * FLATK];        // fc W hi 10.3MB
__device__ float g_hp[(size_t)KSPLIT * BATCH * NPADFC];

// ---------------- init ----------------
__global__ void k_init() {
    int t = threadIdx.x;
    if (t < 2) g_sums[t] = 0.f;
    if (t < OCH) { g_csum[t] = 0.f; g_csumsq[t] = 0.f; }
}

// ---------------- gather + chequer perm + bn0 stats ----------------
__global__ void k_gather(const float* __restrict__ nf, const float* __restrict__ rf,
                         const int* __restrict__ sub, const int* __restrict__ rel) {
    int b = blockIdx.x;
    int t = threadIdx.x;   // 512
    float v = 0.f;
    if (t < NPIX) {
        int r = t / 20, c = t % 20;
        int idx = r * 10 + (c >> 1);
        int useB = (r + c) & 1;
        v = useB ? rf[rel[b] * DIM + idx]
                 : nf[(size_t)sub[b] * DIM + idx];
        g_X[b * NPIX + t] = v;
    }
    __shared__ float ss[512], sq[512];
    ss[t] = v; sq[t] = v * v;
    __syncthreads();
    for (int s = 256; s > 0; s >>= 1) {
        if (t < s) { ss[t] += ss[t + s]; sq[t] += sq[t + s]; }
        __syncthreads();
    }
    if (t == 0) { atomicAdd(&g_sums[0], ss[0]); atomicAdd(&g_sums[1], sq[0]); }
}

// ---------------- conv prologue ----------------
__device__ __forceinline__ void conv_prologue(int b, int t, float* xs, float* fs,
                                              const float* __restrict__ fw,
                                              const int* __restrict__ rel,
                                              const float* __restrict__ bn0g,
                                              const float* __restrict__ bn0b) {
    float invN = 1.0f / (float)(BATCH * NPIX);
    float m0 = g_sums[0] * invN;
    float v0 = g_sums[1] * invN - m0 * m0;
    float sc0 = bn0g[0] * rsqrtf(v0 + EPSF);
    float sh0 = bn0b[0] - sc0 * m0;
    for (int i = t; i < 484; i += 256) {
        int ph = i / 22, pw = i % 22;
        float val = 0.f;
        if (ph >= 1 && ph <= 20 && pw >= 1 && pw <= 20)
            val = sc0 * g_X[b * NPIX + (ph - 1) * 20 + (pw - 1)] + sh0;
        xs[i] = val;
    }
    int rb = rel[b];
    for (int i = t; i < OCH * 9; i += 256) fs[i] = fw[rb * (OCH * 9) + i];
}

__device__ __forceinline__ float conv_at(const float* xs, const float* f, int pix) {
    int h = pix / 20, w = pix % 20;
    const float* xp = &xs[h * 22 + w];
    return xp[0]  * f[0] + xp[1]  * f[1] + xp[2]  * f[2]
         + xp[22] * f[3] + xp[23] * f[4] + xp[24] * f[5]
         + xp[44] * f[6] + xp[45] * f[7] + xp[46] * f[8];
}

// ---------------- conv pass 1: channel stats ----------------
__global__ void k_conv_stats(const float* __restrict__ fw, const int* __restrict__ rel,
                             const float* __restrict__ bn0g, const float* __restrict__ bn0b) {
    int b = blockIdx.x;
    int t = threadIdx.x;
    __shared__ float xs[22 * 22];
    __shared__ float fs[OCH * 9];
    conv_prologue(b, t, xs, fs, fw, rel, bn0g, bn0b);
    __syncthreads();

    int oc = t >> 2, l4 = t & 3;
    float f[9];
#pragma unroll
    for (int j = 0; j < 9; j++) f[j] = fs[oc * 9 + j];

    float s1 = 0.f, s2 = 0.f;
#pragma unroll 4
    for (int s = 0; s < 100; s++) {
        int pix = l4 + 4 * s;
        float acc = conv_at(xs, f, pix);
        s1 += acc; s2 += acc * acc;
    }
    s1 += __shfl_down_sync(0xffffffffu, s1, 2, 4);
    s1 += __shfl_down_sync(0xffffffffu, s1, 1, 4);
    s2 += __shfl_down_sync(0xffffffffu, s2, 2, 4);
    s2 += __shfl_down_sync(0xffffffffu, s2, 1, 4);
    if (l4 == 0) { atomicAdd(&g_csum[oc], s1); atomicAdd(&g_csumsq[oc], s2); }
}

// ---------------- compose BN2d pair ----------------
__global__ void k_chan(const float* __restrict__ cg, const float* __restrict__ cb,
                       const float* __restrict__ b1g, const float* __restrict__ b1b) {
    int t = threadIdx.x;
    if (t >= OCH) return;
    float invN = 1.0f / (float)(BATCH * NPIX);
    float m = g_csum[t] * invN;
    float v = g_csumsq[t] * invN - m * m;
    float t1 = rsqrtf(v + EPSF);
    float var1 = cg[t] * cg[t] * v * t1 * t1;
    float t2 = rsqrtf(var1 + EPSF);
    float sc = b1g[t] * cg[t] * t1 * t2;
    g_scale[t] = sc;
    g_shift[t] = b1b[t] - sc * m;
}

// ---------------- fc_w -> fp16 hi ----------------
__global__ void k_cvt_fcw(const float* __restrict__ fw) {
    int n = blockIdx.x;
    int t = threadIdx.x;
#pragma unroll 4
    for (int i = 0; i < 100; i++) {
        size_t idx = (size_t)n * FLATK + t + 256 * i;
        g_wh[idx] = __float2half_rn(fw[idx]);
    }
}

// ---------------- conv pass 2: fused BN+relu -> fp16 hi/lo, coalesced half2 ----------------
__global__ void k_conv_fused(const float* __restrict__ fw, const int* __restrict__ rel,
                             const float* __restrict__ bn0g, const float* __restrict__ bn0b) {
    int b = blockIdx.x;
    int t = threadIdx.x;   // 256 = 8 warps
    __shared__ float xs[22 * 22];
    __shared__ float fs[OCH * 9];
    conv_prologue(b, t, xs, fs, fw, rel, bn0g, bn0b);
    __syncthreads();

    int lane = t & 31, w = t >> 5;   // warp w owns ocs [8w, 8w+8)
#pragma unroll
    for (int j = 0; j < 8; j++) {
        int oc = w * 8 + j;
        float f[9];
#pragma unroll
        for (int q = 0; q < 9; q++) f[q] = fs[oc * 9 + q];
        float sc = g_scale[oc], sh = g_shift[oc];
        size_t base = ((size_t)b * OCH + oc) * NPIX;
        __half2* dh = (__half2*)(g_yh + base);
        __half2* dl = (__half2*)(g_yl + base);
        // 200 half2 pairs, lanes sweep contiguously -> 128B warp stores
        for (int i = lane; i < 200; i += 32) {
            float a0 = conv_at(xs, f, 2 * i);
            float a1 = conv_at(xs, f, 2 * i + 1);
            float z0 = sc * a0 + sh; z0 = z0 > 0.f ? z0 : 0.f;
            float z1 = sc * a1 + sh; z1 = z1 > 0.f ? z1 : 0.f;
            __half h0 = __float2half_rn(z0);
            __half h1 = __float2half_rn(z1);
            float l0 = z0 - __half2float(h0);
            float l1 = z1 - __half2float(h1);
            dh[i] = __halves2half2(h0, h1);
            dl[i] = __halves2half2(__float2half_rn(l0), __float2half_rn(l1));
        }
    }
}

// ---------------- n_feats -> fp16 hi (padded) ----------------
__global__ void k_cvt_nf(const float* __restrict__ nf) {
    int n = blockIdx.x;      // 0..NENTP-1
    int k = threadIdx.x;     // 0..255
    float x = 0.f;
    if (n < NENT && k < DIM) x = nf[(size_t)n * DIM + k];
    g_bp[(size_t)n * KPASS + k] = __float2half_rn(x);
}

// ---------------- mma helpers ----------------
__device__ __forceinline__ uint32_t cvta_smem(const void* p) {
    uint32_t a;
    asm("{ .reg .u64 t; cvta.to.shared.u64 t, %1; cvt.u32.u64 %0, t; }" : "=r"(a) : "l"(p));
    return a;
}
__device__ __forceinline__ void cp16(uint32_t dst, const void* src, uint32_t sz) {
    asm volatile("cp.async.cg.shared.global [%0], [%1], 16, %2;"
                 :: "r"(dst), "l"(src), "r"(sz));
}
__device__ __forceinline__ void cp_commit() {
    asm volatile("cp.async.commit_group;");
}
template <int N>
__device__ __forceinline__ void cp_wait() {
    asm volatile("cp.async.wait_group %0;" :: "n"(N));
}
__device__ __forceinline__ void ldsm_x4(uint32_t& r0, uint32_t& r1, uint32_t& r2, uint32_t& r3,
                                        uint32_t addr) {
    asm volatile("ldmatrix.sync.aligned.m8n8.x4.shared.b16 {%0,%1,%2,%3}, [%4];"
                 : "=r"(r0), "=r"(r1), "=r"(r2), "=r"(r3) : "r"(addr));
}
__device__ __forceinline__ void mma_f16(float& d0, float& d1, float& d2, float& d3,
                                        uint32_t a0, uint32_t a1, uint32_t a2, uint32_t a3,
                                        uint32_t b0, uint32_t b1) {
    asm volatile("mma.sync.aligned.m16n8k16.row.col.f32.f16.f16.f32 "
                 "{%0,%1,%2,%3}, {%4,%5,%6,%7}, {%8,%9}, {%0,%1,%2,%3};"
                 : "+f"(d0), "+f"(d1), "+f"(d2), "+f"(d3)
                 : "r"(a0), "r"(a1), "r"(a2), "r"(a3), "r"(b0), "r"(b1));
}

// ---------------- FC GEMM: CTA 128Mx256N, 512 threads, single N-tile ----------------
#define FC_ASZ 16384
#define FC_BSZ 32768
#define FC_STG (FC_ASZ + FC_BSZ)    // 48KB per stage

__global__ __launch_bounds__(512, 1) void k_fc_mma() {
    extern __shared__ __align__(1024) unsigned char dsm[];
    int t = threadIdx.x;
    int lane = t & 31, wid = t >> 5;     // 16 warps
    int wm = (wid >> 3) * 64;            // 0 / 64
    int wn = (wid & 7) * 32;             // 0..224
    int m0 = blockIdx.y * 128;
    int ks = blockIdx.z;
    size_t kbase = (size_t)ks * KSEG;

    uint32_t smemBase = cvta_smem(dsm);

    int rowA[2]; uint32_t soA[2]; int segA[2];
#pragma unroll
    for (int r = 0; r < 2; r++) {
        int e = t + 512 * r;
        rowA[r] = e >> 3; segA[r] = e & 7;
        soA[r] = (uint32_t)rowA[r] * 128 + (uint32_t)((segA[r] ^ (rowA[r] & 7)) << 4);
    }
    int rowB[4]; uint32_t soB[4]; int segB[4];
#pragma unroll
    for (int r = 0; r < 4; r++) {
        int e = t + 512 * r;
        rowB[r] = e >> 3; segB[r] = e & 7;
        soB[r] = (uint32_t)rowB[r] * 128 + (uint32_t)((segB[r] ^ (rowB[r] & 7)) << 4);
    }

    int grp = lane >> 3, li = lane & 7;
    int roffA = ((grp & 1) << 3) + li;
    int cgA = grp >> 1;
    int noffB = ((grp >> 1) << 3) + li;
    int cgB = grp & 1;

    float acc[4][4][4];
#pragma unroll
    for (int a = 0; a < 4; a++)
#pragma unroll
        for (int b = 0; b < 4; b++)
#pragma unroll
            for (int c = 0; c < 4; c++) acc[a][b][c] = 0.f;

    auto issue = [&](int idx) {
        int p = idx / 50, c = idx - p * 50;
        const __half* Ab = p ? g_yl : g_yh;
        size_t koff = kbase + (size_t)c * 64;
        uint32_t base = smemBase + (uint32_t)(idx & 1) * FC_STG;
#pragma unroll
        for (int r = 0; r < 2; r++) {
            size_t ga = (size_t)(m0 + rowA[r]) * FLATK + koff + segA[r] * 8;
            cp16(base + soA[r], Ab + ga, 16);
        }
#pragma unroll
        for (int r = 0; r < 4; r++) {
            int nrow = rowB[r];
            int ok = nrow < DIM;
            size_t gb = (size_t)(ok ? nrow : 0) * FLATK + koff + segB[r] * 8;
            cp16(base + FC_ASZ + soB[r], g_wh + gb, ok ? 16u : 0u);
        }
        cp_commit();
    };

    issue(0);
    for (int ch = 0; ch < FC_CHUNKS; ch++) {
        if (ch < FC_CHUNKS - 1) { issue(ch + 1); cp_wait<1>(); }
        else cp_wait<0>();
        __syncthreads();
        uint32_t baseA = smemBase + (uint32_t)(ch & 1) * FC_STG;
        uint32_t baseB = baseA + FC_ASZ;
#pragma unroll
        for (int kf = 0; kf < 4; kf++) {
            uint32_t a[4][4];
#pragma unroll
            for (int mf = 0; mf < 4; mf++) {
                int row = wm + mf * 16 + roffA;
                uint32_t addr = baseA + (uint32_t)row * 128
                              + (uint32_t)(((kf * 2 + cgA) ^ li) << 4);
                ldsm_x4(a[mf][0], a[mf][1], a[mf][2], a[mf][3], addr);
            }
            uint32_t b[4][2];
#pragma unroll
            for (int nf2 = 0; nf2 < 2; nf2++) {
                int row = wn + nf2 * 16 + noffB;
                uint32_t addr = baseB + (uint32_t)row * 128
                              + (uint32_t)(((kf * 2 + cgB) ^ li) << 4);
                ldsm_x4(b[nf2 * 2][0], b[nf2 * 2][1], b[nf2 * 2 + 1][0], b[nf2 * 2 + 1][1], addr);
            }
#pragma unroll
            for (int mf = 0; mf < 4; mf++)
#pragma unroll
                for (int nf = 0; nf < 4; nf++)
                    mma_f16(acc[mf][nf][0], acc[mf][nf][1], acc[mf][nf][2], acc[mf][nf][3],
                            a[mf][0], a[mf][1], a[mf][2], a[mf][3],
                            b[nf][0], b[nf][1]);
        }
        __syncthreads();
    }

    int g = lane >> 2, c = lane & 3;
    float* hp = g_hp + (size_t)ks * BATCH * NPADFC;
#pragma unroll
    for (int mf = 0; mf < 4; mf++) {
#pragma unroll
        for (int nf = 0; nf < 4; nf++) {
            int n = wn + nf * 8 + c * 2;
            int m = m0 + wm + mf * 16 + g;
            float2 v0 = {acc[mf][nf][0], acc[mf][nf][1]};
            *(float2*)(hp + (size_t)m * NPADFC + n) = v0;
            float2 v1 = {acc[mf][nf][2], acc[mf][nf][3]};
            *(float2*)(hp + (size_t)(m + 8) * NPADFC + n) = v1;
        }
    }
}

// ---------------- reduce fc partials + bias ----------------
__global__ void k_fcred(const float* __restrict__ fb) {
    int m = blockIdx.x;
    int t = threadIdx.x;
    if (t >= DIM) return;
    float s = fb[t];
#pragma unroll
    for (int z = 0; z < KSPLIT; z++)
        s += g_hp[((size_t)z * BATCH + m) * NPADFC + t];
    g_H[m * DIM + t] = s;
}

// ---------------- bn1d + relu -> A' = [Ah | Al] fp16 ----------------
__global__ void k_bn1d(const float* __restrict__ b2g, const float* __restrict__ b2b) {
    int d = blockIdx.x;     // 0..255
    int t = threadIdx.x;    // 256
    __half z16 = __float2half_rn(0.f);
    if (d >= DIM) {
        for (int i = t; i < BATCH; i += 256) {
            size_t base = (size_t)i * KTOT2 + d;
            g_ap[base] = z16; g_ap[base + KPASS] = z16;
        }
        return;
    }
    float vals[8];
    float s1 = 0.f, s2 = 0.f;
#pragma unroll
    for (int i = 0; i < 8; i++) {
        float h = g_H[(t + 256 * i) * DIM + d];
        vals[i] = h; s1 += h; s2 += h * h;
    }
    __shared__ float ss[256], sq[256];
    ss[t] = s1; sq[t] = s2;
    __syncthreads();
    for (int s = 128; s > 0; s >>= 1) {
        if (t < s) { ss[t] += ss[t + s]; sq[t] += sq[t + s]; }
        __syncthreads();
    }
    __shared__ float ssc, ssh;
    if (t == 0) {
        float m = ss[0] / (float)BATCH;
        float v = sq[0] / (float)BATCH - m * m;
        float sc = b2g[d] * rsqrtf(v + EPSF);
        ssc = sc; ssh = b2b[d] - sc * m;
    }
    __syncthreads();
    float sc = ssc, sh = ssh;
#pragma unroll
    for (int i = 0; i < 8; i++) {
        float z = sc * vals[i] + sh;
        z = z > 0.f ? z : 0.f;
        __half hi = __float2half_rn(z);
        size_t base = (size_t)(t + 256 * i) * KTOT2 + d;
        g_ap[base] = hi;
        g_ap[base + KPASS] = __float2half_rn(z - __half2float(hi));
    }
}

// ---------------- scoring GEMM: fp16 2-pass, K'=512 (proven config) ----------------
#define STAGE_BYTES 32768

__global__ __launch_bounds__(256, 2) void k_out_mma(const float* __restrict__ eb,
                                                    float* __restrict__ out) {
    extern __shared__ __align__(1024) unsigned char dsm[];
    int t = threadIdx.x;
    int lane = t & 31, wid = t >> 5;
    int wm = (wid >> 2) * 64;
    int wn = (wid & 3) * 32;
    int m0 = blockIdx.x * 128;
    int n0 = blockIdx.y * NTILE;

    uint32_t smemBase = cvta_smem(dsm);

    int rowL[4]; uint32_t soL[4]; int segL[4];
#pragma unroll
    for (int r = 0; r < 4; r++) {
        int e = t + 256 * r;
        rowL[r] = e >> 3;
        segL[r] = e & 7;
        soL[r] = (uint32_t)rowL[r] * 128 + (uint32_t)((segL[r] ^ (rowL[r] & 7)) << 4);
    }
    const __half* pA = g_ap + (size_t)m0 * KTOT2;
    const __half* pB = g_bp + (size_t)n0 * KPASS;

    int grp = lane >> 3, li = lane & 7;
    int roffA = ((grp & 1) << 3) + li;
    int cgA = grp >> 1;
    int noffB = ((grp >> 1) << 3) + li;
    int cgB = grp & 1;

    float acc[4][4][4];
#pragma unroll
    for (int a = 0; a < 4; a++)
#pragma unroll
        for (int b = 0; b < 4; b++)
#pragma unroll
            for (int c = 0; c < 4; c++) acc[a][b][c] = 0.f;

    auto issue = [&](int ch) {
        uint32_t base = smemBase + (uint32_t)(ch & 1) * STAGE_BYTES;
        int cb = ch & 3;   // B repeats over the two passes
#pragma unroll
        for (int r = 0; r < 4; r++) {
            size_t ga = (size_t)rowL[r] * KTOT2 + ch * 64 + segL[r] * 8;
            cp16(base + soL[r], pA + ga, 16);
            size_t gb = (size_t)rowL[r] * KPASS + cb * 64 + segL[r] * 8;
            cp16(base + 16384 + soL[r], pB + gb, 16);
        }
        cp_commit();
    };

    issue(0);
    for (int ch = 0; ch < 8; ch++) {
        if (ch < 7) { issue(ch + 1); cp_wait<1>(); }
        else cp_wait<0>();
        __syncthreads();
        uint32_t baseA = smemBase + (uint32_t)(ch & 1) * STAGE_BYTES;
        uint32_t baseB = baseA + 16384;
#pragma unroll
        for (int kf = 0; kf < 4; kf++) {
            uint32_t a[4][4];
#pragma unroll
            for (int mf = 0; mf < 4; mf++) {
                int row = wm + mf * 16 + roffA;
                uint32_t addr = baseA + (uint32_t)row * 128
                              + (uint32_t)(((kf * 2 + cgA) ^ li) << 4);
                ldsm_x4(a[mf][0], a[mf][1], a[mf][2], a[mf][3], addr);
            }
            uint32_t b[4][2];
#pragma unroll
            for (int nf2 = 0; nf2 < 2; nf2++) {
                int row = wn + nf2 * 16 + noffB;
                uint32_t addr = baseB + (uint32_t)row * 128
                              + (uint32_t)(((kf * 2 + cgB) ^ li) << 4);
                ldsm_x4(b[nf2 * 2][0], b[nf2 * 2][1], b[nf2 * 2 + 1][0], b[nf2 * 2 + 1][1], addr);
            }
#pragma unroll
            for (int mf = 0; mf < 4; mf++)
#pragma unroll
                for (int nf = 0; nf < 4; nf++)
                    mma_f16(acc[mf][nf][0], acc[mf][nf][1], acc[mf][nf][2], acc[mf][nf][3],
                            a[mf][0], a[mf][1], a[mf][2], a[mf][3],
                            b[nf][0], b[nf][1]);
        }
        __syncthreads();
    }

    int g = lane >> 2, c = lane & 3;
#pragma unroll
    for (int mf = 0; mf < 4; mf++) {
#pragma unroll
        for (int nf = 0; nf < 4; nf++) {
            int n = n0 + wn + nf * 8 + c * 2;
            if (n < NENT) {
                float2 bias = *(const float2*)(eb + n);
                int m = m0 + wm + mf * 16 + g;
                float2 v0 = {acc[mf][nf][0] + bias.x, acc[mf][nf][1] + bias.y};
                *(float2*)(out + (size_t)m * NENT + n) = v0;
                float2 v1 = {acc[mf][nf][2] + bias.x, acc[mf][nf][3] + bias.y};
                *(float2*)(out + (size_t)(m + 8) * NENT + n) = v1;
            }
        }
    }
}

// ---------------- launch ----------------
extern "C" void kernel_launch(void* const* d_in, const int* in_sizes, int n_in,
                              void* d_out, int out_size) {
    const float* nf   = (const float*)d_in[0];
    const float* rf   = (const float*)d_in[1];
    const float* fw   = (const float*)d_in[2];
    const float* bn0g = (const float*)d_in[3];
    const float* bn0b = (const float*)d_in[4];
    const float* cbng = (const float*)d_in[5];
    const float* cbnb = (const float*)d_in[6];
    const float* bn1g = (const float*)d_in[7];
    const float* bn1b = (const float*)d_in[8];
    const float* fcw  = (const float*)d_in[9];
    const float* fcb  = (const float*)d_in[10];
    const float* bn2g = (const float*)d_in[11];
    const float* bn2b = (const float*)d_in[12];
    const float* eb   = (const float*)d_in[13];
    const int*   sub  = (const int*)d_in[14];
    const int*   rel  = (const int*)d_in[15];
    float* out = (float*)d_out;

    cudaFuncSetAttribute(k_out_mma, cudaFuncAttributeMaxDynamicSharedMemorySize, 2 * STAGE_BYTES);
    cudaFuncSetAttribute(k_fc_mma, cudaFuncAttributeMaxDynamicSharedMemorySize, 2 * FC_STG);

    k_init<<<1, 256>>>();
    k_gather<<<BATCH, 512>>>(nf, rf, sub, rel);
    k_conv_stats<<<BATCH, 256>>>(fw, rel, bn0g, bn0b);
    k_chan<<<1, 64>>>(cbng, cbnb, bn1g, bn1b);
    k_cvt_fcw<<<DIM, 256>>>(fcw);
    k_conv_fused<<<BATCH, 256>>>(fw, rel, bn0g, bn0b);
    k_cvt_nf<<<NENTP, 256>>>(nf);
    k_fc_mma<<<dim3(1, 16, KSPLIT), 512, 2 * FC_STG>>>();
    k_fcred<<<BATCH, 256>>>(fcb);
    k_bn1d<<<KPASS, 256>>>(bn2g, bn2b);
    k_out_mma<<<dim3(16, NTILES), 256, 2 * STAGE_BYTES>>>(eb, out);
}

// round 12
// speedup vs baseline: 1.5151x; 1.3602x over previous
#include <cuda_runtime.h>
#include <cuda_fp16.h>
#include <math.h>
#include <stdint.h>

#define BATCH   2048
#define DIM     200
#define OCH     64
#define NPIX    400          // 20x20
#define FLATK   25600        // 64*400
#define NENT    50000
#define EPSF    1e-5f

#define KPASS   256          // padded K (200 -> 256)
#define NTILE   128
#define NTILES  391
#define NENTP   (NTILES*NTILE)   // 50048
#define KSPLIT  8
#define KSEG    (FLATK/KSPLIT)   // 3200
#define NPADFC  256
#define FC_CHUNKS 50         // single fp16 pass

// ---------------- scratch ----------------
__device__ float g_X[BATCH * NPIX];
__device__ float g_H[BATCH * DIM];
__device__ float g_sums[2];
__device__ float g_csum[OCH];
__device__ float g_csumsq[OCH];
__device__ float g_scale[OCH];
__device__ float g_shift[OCH];
__device__ __half g_ap[(size_t)BATCH * KPASS];      // scoring A (hi) 1MB
__device__ __half g_bp[(size_t)NENTP * KPASS];      // scoring B (hi) 25.6MB
__device__ __half g_yh[(size_t)BATCH * FLATK];      // fc A hi 105MB
__device__ __half g_wh[(size_t)DIM * FLATK];        // fc W hi 10.3MB
__device__ float g_hp[(size_t)KSPLIT * BATCH * NPADFC];

// ---------------- init ----------------
__global__ void k_init() {
    int t = threadIdx.x;
    if (t < 2) g_sums[t] = 0.f;
    if (t < OCH) { g_csum[t] = 0.f; g_csumsq[t] = 0.f; }
}

// ---------------- gather + chequer perm + bn0 stats ----------------
__global__ void k_gather(const float* __restrict__ nf, const float* __restrict__ rf,
                         const int* __restrict__ sub, const int* __restrict__ rel) {
    int b = blockIdx.x;
    int t = threadIdx.x;   // 512
    float v = 0.f;
    if (t < NPIX) {
        int r = t / 20, c = t % 20;
        int idx = r * 10 + (c >> 1);
        int useB = (r + c) & 1;
        v = useB ? rf[rel[b] * DIM + idx]
                 : nf[(size_t)sub[b] * DIM + idx];
        g_X[b * NPIX + t] = v;
    }
    __shared__ float ss[512], sq[512];
    ss[t] = v; sq[t] = v * v;
    __syncthreads();
    for (int s = 256; s > 0; s >>= 1) {
        if (t < s) { ss[t] += ss[t + s]; sq[t] += sq[t + s]; }
        __syncthreads();
    }
    if (t == 0) { atomicAdd(&g_sums[0], ss[0]); atomicAdd(&g_sums[1], sq[0]); }
}

// ---------------- conv prologue ----------------
__device__ __forceinline__ void conv_prologue(int b, int t, float* xs, float* fs,
                                              const float* __restrict__ fw,
                                              const int* __restrict__ rel,
                                              const float* __restrict__ bn0g,
                                              const float* __restrict__ bn0b) {
    float invN = 1.0f / (float)(BATCH * NPIX);
    float m0 = g_sums[0] * invN;
    float v0 = g_sums[1] * invN - m0 * m0;
    float sc0 = bn0g[0] * rsqrtf(v0 + EPSF);
    float sh0 = bn0b[0] - sc0 * m0;
    for (int i = t; i < 484; i += 256) {
        int ph = i / 22, pw = i % 22;
        float val = 0.f;
        if (ph >= 1 && ph <= 20 && pw >= 1 && pw <= 20)
            val = sc0 * g_X[b * NPIX + (ph - 1) * 20 + (pw - 1)] + sh0;
        xs[i] = val;
    }
    int rb = rel[b];
    for (int i = t; i < OCH * 9; i += 256) fs[i] = fw[rb * (OCH * 9) + i];
}

__device__ __forceinline__ float conv_at(const float* xs, const float* f, int pix) {
    int h = pix / 20, w = pix % 20;
    const float* xp = &xs[h * 22 + w];
    return xp[0]  * f[0] + xp[1]  * f[1] + xp[2]  * f[2]
         + xp[22] * f[3] + xp[23] * f[4] + xp[24] * f[5]
         + xp[44] * f[6] + xp[45] * f[7] + xp[46] * f[8];
}

// ---------------- conv pass 1: channel stats ----------------
__global__ void k_conv_stats(const float* __restrict__ fw, const int* __restrict__ rel,
                             const float* __restrict__ bn0g, const float* __restrict__ bn0b) {
    int b = blockIdx.x;
    int t = threadIdx.x;
    __shared__ float xs[22 * 22];
    __shared__ float fs[OCH * 9];
    conv_prologue(b, t, xs, fs, fw, rel, bn0g, bn0b);
    __syncthreads();

    int oc = t >> 2, l4 = t & 3;
    float f[9];
#pragma unroll
    for (int j = 0; j < 9; j++) f[j] = fs[oc * 9 + j];

    float s1 = 0.f, s2 = 0.f;
#pragma unroll 4
    for (int s = 0; s < 100; s++) {
        int pix = l4 + 4 * s;
        float acc = conv_at(xs, f, pix);
        s1 += acc; s2 += acc * acc;
    }
    s1 += __shfl_down_sync(0xffffffffu, s1, 2, 4);
    s1 += __shfl_down_sync(0xffffffffu, s1, 1, 4);
    s2 += __shfl_down_sync(0xffffffffu, s2, 2, 4);
    s2 += __shfl_down_sync(0xffffffffu, s2, 1, 4);
    if (l4 == 0) { atomicAdd(&g_csum[oc], s1); atomicAdd(&g_csumsq[oc], s2); }
}

// ---------------- compose BN2d pair ----------------
__global__ void k_chan(const float* __restrict__ cg, const float* __restrict__ cb,
                       const float* __restrict__ b1g, const float* __restrict__ b1b) {
    int t = threadIdx.x;
    if (t >= OCH) return;
    float invN = 1.0f / (float)(BATCH * NPIX);
    float m = g_csum[t] * invN;
    float v = g_csumsq[t] * invN - m * m;
    float t1 = rsqrtf(v + EPSF);
    float var1 = cg[t] * cg[t] * v * t1 * t1;
    float t2 = rsqrtf(var1 + EPSF);
    float sc = b1g[t] * cg[t] * t1 * t2;
    g_scale[t] = sc;
    g_shift[t] = b1b[t] - sc * m;
}

// ---------------- fc_w -> fp16 hi ----------------
__global__ void k_cvt_fcw(const float* __restrict__ fw) {
    int n = blockIdx.x;
    int t = threadIdx.x;
#pragma unroll 4
    for (int i = 0; i < 100; i++) {
        size_t idx = (size_t)n * FLATK + t + 256 * i;
        g_wh[idx] = __float2half_rn(fw[idx]);
    }
}

// ---------------- conv pass 2: fused BN+relu -> fp16 (hi only), coalesced ----------------
__global__ void k_conv_fused(const float* __restrict__ fw, const int* __restrict__ rel,
                             const float* __restrict__ bn0g, const float* __restrict__ bn0b) {
    int b = blockIdx.x;
    int t = threadIdx.x;   // 256 = 8 warps
    __shared__ float xs[22 * 22];
    __shared__ float fs[OCH * 9];
    conv_prologue(b, t, xs, fs, fw, rel, bn0g, bn0b);
    __syncthreads();

    int lane = t & 31, w = t >> 5;   // warp w owns ocs [8w, 8w+8)
#pragma unroll
    for (int j = 0; j < 8; j++) {
        int oc = w * 8 + j;
        float f[9];
#pragma unroll
        for (int q = 0; q < 9; q++) f[q] = fs[oc * 9 + q];
        float sc = g_scale[oc], sh = g_shift[oc];
        size_t base = ((size_t)b * OCH + oc) * NPIX;
        __half2* dh = (__half2*)(g_yh + base);
        for (int i = lane; i < 200; i += 32) {
            float a0 = conv_at(xs, f, 2 * i);
            float a1 = conv_at(xs, f, 2 * i + 1);
            float z0 = sc * a0 + sh; z0 = z0 > 0.f ? z0 : 0.f;
            float z1 = sc * a1 + sh; z1 = z1 > 0.f ? z1 : 0.f;
            dh[i] = __halves2half2(__float2half_rn(z0), __float2half_rn(z1));
        }
    }
}

// ---------------- n_feats -> fp16 hi (padded) ----------------
__global__ void k_cvt_nf(const float* __restrict__ nf) {
    int n = blockIdx.x;      // 0..NENTP-1
    int k = threadIdx.x;     // 0..255
    float x = 0.f;
    if (n < NENT && k < DIM) x = nf[(size_t)n * DIM + k];
    g_bp[(size_t)n * KPASS + k] = __float2half_rn(x);
}

// ---------------- mma helpers ----------------
__device__ __forceinline__ uint32_t cvta_smem(const void* p) {
    uint32_t a;
    asm("{ .reg .u64 t; cvta.to.shared.u64 t, %1; cvt.u32.u64 %0, t; }" : "=r"(a) : "l"(p));
    return a;
}
__device__ __forceinline__ void cp16(uint32_t dst, const void* src, uint32_t sz) {
    asm volatile("cp.async.cg.shared.global [%0], [%1], 16, %2;"
                 :: "r"(dst), "l"(src), "r"(sz));
}
__device__ __forceinline__ void cp_commit() {
    asm volatile("cp.async.commit_group;");
}
template <int N>
__device__ __forceinline__ void cp_wait() {
    asm volatile("cp.async.wait_group %0;" :: "n"(N));
}
__device__ __forceinline__ void ldsm_x4(uint32_t& r0, uint32_t& r1, uint32_t& r2, uint32_t& r3,
                                        uint32_t addr) {
    asm volatile("ldmatrix.sync.aligned.m8n8.x4.shared.b16 {%0,%1,%2,%3}, [%4];"
                 : "=r"(r0), "=r"(r1), "=r"(r2), "=r"(r3) : "r"(addr));
}
__device__ __forceinline__ void mma_f16(float& d0, float& d1, float& d2, float& d3,
                                        uint32_t a0, uint32_t a1, uint32_t a2, uint32_t a3,
                                        uint32_t b0, uint32_t b1) {
    asm volatile("mma.sync.aligned.m16n8k16.row.col.f32.f16.f16.f32 "
                 "{%0,%1,%2,%3}, {%4,%5,%6,%7}, {%8,%9}, {%0,%1,%2,%3};"
                 : "+f"(d0), "+f"(d1), "+f"(d2), "+f"(d3)
                 : "r"(a0), "r"(a1), "r"(a2), "r"(a3), "r"(b0), "r"(b1));
}

// ---------------- FC GEMM: CTA 128Mx256N, 512 threads, single pass ----------------
#define FC_ASZ 16384
#define FC_BSZ 32768
#define FC_STG (FC_ASZ + FC_BSZ)    // 48KB per stage

__global__ __launch_bounds__(512, 1) void k_fc_mma() {
    extern __shared__ __align__(1024) unsigned char dsm[];
    int t = threadIdx.x;
    int lane = t & 31, wid = t >> 5;     // 16 warps
    int wm = (wid >> 3) * 64;            // 0 / 64
    int wn = (wid & 7) * 32;             // 0..224
    int m0 = blockIdx.y * 128;
    int ks = blockIdx.z;
    size_t kbase = (size_t)ks * KSEG;

    uint32_t smemBase = cvta_smem(dsm);

    int rowA[2]; uint32_t soA[2]; int segA[2];
#pragma unroll
    for (int r = 0; r < 2; r++) {
        int e = t + 512 * r;
        rowA[r] = e >> 3; segA[r] = e & 7;
        soA[r] = (uint32_t)rowA[r] * 128 + (uint32_t)((segA[r] ^ (rowA[r] & 7)) << 4);
    }
    int rowB[4]; uint32_t soB[4]; int segB[4];
#pragma unroll
    for (int r = 0; r < 4; r++) {
        int e = t + 512 * r;
        rowB[r] = e >> 3; segB[r] = e & 7;
        soB[r] = (uint32_t)rowB[r] * 128 + (uint32_t)((segB[r] ^ (rowB[r] & 7)) << 4);
    }

    int grp = lane >> 3, li = lane & 7;
    int roffA = ((grp & 1) << 3) + li;
    int cgA = grp >> 1;
    int noffB = ((grp >> 1) << 3) + li;
    int cgB = grp & 1;

    float acc[4][4][4];
#pragma unroll
    for (int a = 0; a < 4; a++)
#pragma unroll
        for (int b = 0; b < 4; b++)
#pragma unroll
            for (int c = 0; c < 4; c++) acc[a][b][c] = 0.f;

    auto issue = [&](int idx) {
        size_t koff = kbase + (size_t)idx * 64;
        uint32_t base = smemBase + (uint32_t)(idx & 1) * FC_STG;
#pragma unroll
        for (int r = 0; r < 2; r++) {
            size_t ga = (size_t)(m0 + rowA[r]) * FLATK + koff + segA[r] * 8;
            cp16(base + soA[r], g_yh + ga, 16);
        }
#pragma unroll
        for (int r = 0; r < 4; r++) {
            int nrow = rowB[r];
            int ok = nrow < DIM;
            size_t gb = (size_t)(ok ? nrow : 0) * FLATK + koff + segB[r] * 8;
            cp16(base + FC_ASZ + soB[r], g_wh + gb, ok ? 16u : 0u);
        }
        cp_commit();
    };

    issue(0);
    for (int ch = 0; ch < FC_CHUNKS; ch++) {
        if (ch < FC_CHUNKS - 1) { issue(ch + 1); cp_wait<1>(); }
        else cp_wait<0>();
        __syncthreads();
        uint32_t baseA = smemBase + (uint32_t)(ch & 1) * FC_STG;
        uint32_t baseB = baseA + FC_ASZ;
#pragma unroll
        for (int kf = 0; kf < 4; kf++) {
            uint32_t a[4][4];
#pragma unroll
            for (int mf = 0; mf < 4; mf++) {
                int row = wm + mf * 16 + roffA;
                uint32_t addr = baseA + (uint32_t)row * 128
                              + (uint32_t)(((kf * 2 + cgA) ^ li) << 4);
                ldsm_x4(a[mf][0], a[mf][1], a[mf][2], a[mf][3], addr);
            }
            uint32_t b[4][2];
#pragma unroll
            for (int nf2 = 0; nf2 < 2; nf2++) {
                int row = wn + nf2 * 16 + noffB;
                uint32_t addr = baseB + (uint32_t)row * 128
                              + (uint32_t)(((kf * 2 + cgB) ^ li) << 4);
                ldsm_x4(b[nf2 * 2][0], b[nf2 * 2][1], b[nf2 * 2 + 1][0], b[nf2 * 2 + 1][1], addr);
            }
#pragma unroll
            for (int mf = 0; mf < 4; mf++)
#pragma unroll
                for (int nf = 0; nf < 4; nf++)
                    mma_f16(acc[mf][nf][0], acc[mf][nf][1], acc[mf][nf][2], acc[mf][nf][3],
                            a[mf][0], a[mf][1], a[mf][2], a[mf][3],
                            b[nf][0], b[nf][1]);
        }
        __syncthreads();
    }

    int g = lane >> 2, c = lane & 3;
    float* hp = g_hp + (size_t)ks * BATCH * NPADFC;
#pragma unroll
    for (int mf = 0; mf < 4; mf++) {
#pragma unroll
        for (int nf = 0; nf < 4; nf++) {
            int n = wn + nf * 8 + c * 2;
            int m = m0 + wm + mf * 16 + g;
            float2 v0 = {acc[mf][nf][0], acc[mf][nf][1]};
            *(float2*)(hp + (size_t)m * NPADFC + n) = v0;
            float2 v1 = {acc[mf][nf][2], acc[mf][nf][3]};
            *(float2*)(hp + (size_t)(m + 8) * NPADFC + n) = v1;
        }
    }
}

// ---------------- reduce fc partials + bias ----------------
__global__ void k_fcred(const float* __restrict__ fb) {
    int m = blockIdx.x;
    int t = threadIdx.x;
    if (t >= DIM) return;
    float s = fb[t];
#pragma unroll
    for (int z = 0; z < KSPLIT; z++)
        s += g_hp[((size_t)z * BATCH + m) * NPADFC + t];
    g_H[m * DIM + t] = s;
}

// ---------------- bn1d + relu -> A (hi only, padded) ----------------
__global__ void k_bn1d(const float* __restrict__ b2g, const float* __restrict__ b2b) {
    int d = blockIdx.x;     // 0..255
    int t = threadIdx.x;    // 256
    if (d >= DIM) {
        __half z16 = __float2half_rn(0.f);
        for (int i = t; i < BATCH; i += 256)
            g_ap[(size_t)i * KPASS + d] = z16;
        return;
    }
    float vals[8];
    float s1 = 0.f, s2 = 0.f;
#pragma unroll
    for (int i = 0; i < 8; i++) {
        float h = g_H[(t + 256 * i) * DIM + d];
        vals[i] = h; s1 += h; s2 += h * h;
    }
    __shared__ float ss[256], sq[256];
    ss[t] = s1; sq[t] = s2;
    __syncthreads();
    for (int s = 128; s > 0; s >>= 1) {
        if (t < s) { ss[t] += ss[t + s]; sq[t] += sq[t + s]; }
        __syncthreads();
    }
    __shared__ float ssc, ssh;
    if (t == 0) {
        float m = ss[0] / (float)BATCH;
        float v = sq[0] / (float)BATCH - m * m;
        float sc = b2g[d] * rsqrtf(v + EPSF);
        ssc = sc; ssh = b2b[d] - sc * m;
    }
    __syncthreads();
    float sc = ssc, sh = ssh;
#pragma unroll
    for (int i = 0; i < 8; i++) {
        float z = sc * vals[i] + sh;
        z = z > 0.f ? z : 0.f;
        g_ap[(size_t)(t + 256 * i) * KPASS + d] = __float2half_rn(z);
    }
}

// ---------------- scoring GEMM: fp16 single pass, K=256 ----------------
#define STAGE_BYTES 32768

__global__ __launch_bounds__(256, 2) void k_out_mma(const float* __restrict__ eb,
                                                    float* __restrict__ out) {
    extern __shared__ __align__(1024) unsigned char dsm[];
    int t = threadIdx.x;
    int lane = t & 31, wid = t >> 5;
    int wm = (wid >> 2) * 64;
    int wn = (wid & 3) * 32;
    int m0 = blockIdx.x * 128;
    int n0 = blockIdx.y * NTILE;

    uint32_t smemBase = cvta_smem(dsm);

    int rowL[4]; uint32_t soL[4]; int segL[4];
#pragma unroll
    for (int r = 0; r < 4; r++) {
        int e = t + 256 * r;
        rowL[r] = e >> 3;
        segL[r] = e & 7;
        soL[r] = (uint32_t)rowL[r] * 128 + (uint32_t)((segL[r] ^ (rowL[r] & 7)) << 4);
    }
    const __half* pA = g_ap + (size_t)m0 * KPASS;
    const __half* pB = g_bp + (size_t)n0 * KPASS;

    int grp = lane >> 3, li = lane & 7;
    int roffA = ((grp & 1) << 3) + li;
    int cgA = grp >> 1;
    int noffB = ((grp >> 1) << 3) + li;
    int cgB = grp & 1;

    float acc[4][4][4];
#pragma unroll
    for (int a = 0; a < 4; a++)
#pragma unroll
        for (int b = 0; b < 4; b++)
#pragma unroll
            for (int c = 0; c < 4; c++) acc[a][b][c] = 0.f;

    auto issue = [&](int ch) {
        uint32_t base = smemBase + (uint32_t)(ch & 1) * STAGE_BYTES;
#pragma unroll
        for (int r = 0; r < 4; r++) {
            size_t ga = (size_t)rowL[r] * KPASS + ch * 64 + segL[r] * 8;
            cp16(base + soL[r], pA + ga, 16);
            size_t gb = (size_t)rowL[r] * KPASS + ch * 64 + segL[r] * 8;
            cp16(base + 16384 + soL[r], pB + gb, 16);
        }
        cp_commit();
    };

    issue(0);
    for (int ch = 0; ch < 4; ch++) {
        if (ch < 3) { issue(ch + 1); cp_wait<1>(); }
        else cp_wait<0>();
        __syncthreads();
        uint32_t baseA = smemBase + (uint32_t)(ch & 1) * STAGE_BYTES;
        uint32_t baseB = baseA + 16384;
#pragma unroll
        for (int kf = 0; kf < 4; kf++) {
            uint32_t a[4][4];
#pragma unroll
            for (int mf = 0; mf < 4; mf++) {
                int row = wm + mf * 16 + roffA;
                uint32_t addr = baseA + (uint32_t)row * 128
                              + (uint32_t)(((kf * 2 + cgA) ^ li) << 4);
                ldsm_x4(a[mf][0], a[mf][1], a[mf][2], a[mf][3], addr);
            }
            uint32_t b[4][2];
#pragma unroll
            for (int nf2 = 0; nf2 < 2; nf2++) {
                int row = wn + nf2 * 16 + noffB;
                uint32_t addr = baseB + (uint32_t)row * 128
                              + (uint32_t)(((kf * 2 + cgB) ^ li) << 4);
                ldsm_x4(b[nf2 * 2][0], b[nf2 * 2][1], b[nf2 * 2 + 1][0], b[nf2 * 2 + 1][1], addr);
            }
#pragma unroll
            for (int mf = 0; mf < 4; mf++)
#pragma unroll
                for (int nf = 0; nf < 4; nf++)
                    mma_f16(acc[mf][nf][0], acc[mf][nf][1], acc[mf][nf][2], acc[mf][nf][3],
                            a[mf][0], a[mf][1], a[mf][2], a[mf][3],
                            b[nf][0], b[nf][1]);
        }
        __syncthreads();
    }

    int g = lane >> 2, c = lane & 3;
#pragma unroll
    for (int mf = 0; mf < 4; mf++) {
#pragma unroll
        for (int nf = 0; nf < 4; nf++) {
            int n = n0 + wn + nf * 8 + c * 2;
            if (n < NENT) {
                float2 bias = *(const float2*)(eb + n);
                int m = m0 + wm + mf * 16 + g;
                float2 v0 = {acc[mf][nf][0] + bias.x, acc[mf][nf][1] + bias.y};
                *(float2*)(out + (size_t)m * NENT + n) = v0;
                float2 v1 = {acc[mf][nf][2] + bias.x, acc[mf][nf][3] + bias.y};
                *(float2*)(out + (size_t)(m + 8) * NENT + n) = v1;
            }
        }
    }
}

// ---------------- launch ----------------
extern "C" void kernel_launch(void* const* d_in, const int* in_sizes, int n_in,
                              void* d_out, int out_size) {
    const float* nf   = (const float*)d_in[0];
    const float* rf   = (const float*)d_in[1];
    const float* fw   = (const float*)d_in[2];
    const float* bn0g = (const float*)d_in[3];
    const float* bn0b = (const float*)d_in[4];
    const float* cbng = (const float*)d_in[5];
    const float* cbnb = (const float*)d_in[6];
    const float* bn1g = (const float*)d_in[7];
    const float* bn1b = (const float*)d_in[8];
    const float* fcw  = (const float*)d_in[9];
    const float* fcb  = (const float*)d_in[10];
    const float* bn2g = (const float*)d_in[11];
    const float* bn2b = (const float*)d_in[12];
    const float* eb   = (const float*)d_in[13];
    const int*   sub  = (const int*)d_in[14];
    const int*   rel  = (const int*)d_in[15];
    float* out = (float*)d_out;

    cudaFuncSetAttribute(k_out_mma, cudaFuncAttributeMaxDynamicSharedMemorySize, 2 * STAGE_BYTES);
    cudaFuncSetAttribute(k_fc_mma, cudaFuncAttributeMaxDynamicSharedMemorySize, 2 * FC_STG);

    k_init<<<1, 256>>>();
    k_gather<<<BATCH, 512>>>(nf, rf, sub, rel);
    k_conv_stats<<<BATCH, 256>>>(fw, rel, bn0g, bn0b);
    k_chan<<<1, 64>>>(cbng, cbnb, bn1g, bn1b);
    k_cvt_fcw<<<DIM, 256>>>(fcw);
    k_conv_fused<<<BATCH, 256>>>(fw, rel, bn0g, bn0b);
    k_cvt_nf<<<NENTP, 256>>>(nf);
    k_fc_mma<<<dim3(1, 16, KSPLIT), 512, 2 * FC_STG>>>();
    k_fcred<<<BATCH, 256>>>(fcb);
    k_bn1d<<<KPASS, 256>>>(bn2g, bn2b);
    k_out_mma<<<dim3(16, NTILES), 256, 2 * STAGE_BYTES>>>(eb, out);
}

// round 13
// speedup vs baseline: 1.5821x; 1.0442x over previous
#include <cuda_runtime.h>
#include <cuda_fp16.h>
#include <math.h>
#include <stdint.h>

#define BATCH   2048
#define DIM     200
#define OCH     64
#define NPIX    400          // 20x20
#define FLATK   25600        // 64*400
#define NENT    50000
#define EPSF    1e-5f

#define KPASS   256          // padded K storage (200 -> 256)
#define NTILE   128
#define NTILES  391
#define NENTP   (NTILES*NTILE)   // 50048
#define KSPLIT  8
#define KSEG    (FLATK/KSPLIT)   // 3200
#define NPADFC  256
#define FC_CHUNKS 50         // single fp16 pass

// ---------------- scratch ----------------
__device__ float g_X[BATCH * NPIX];
__device__ float g_H[BATCH * DIM];
__device__ float g_sums[2];
__device__ float g_csum[OCH];
__device__ float g_csumsq[OCH];
__device__ __half g_ap[(size_t)BATCH * KPASS];      // scoring A (hi) 1MB
__device__ __half g_bp[(size_t)NENTP * KPASS];      // scoring B (hi) 25.6MB
__device__ __half g_yh[(size_t)BATCH * FLATK];      // fc A 105MB
__device__ __half g_wh[(size_t)DIM * FLATK];        // fc W 10.3MB
__device__ float g_hp[(size_t)KSPLIT * BATCH * NPADFC];

// ---------------- init ----------------
__global__ void k_init() {
    int t = threadIdx.x;
    if (t < 2) g_sums[t] = 0.f;
    if (t < OCH) { g_csum[t] = 0.f; g_csumsq[t] = 0.f; }
}

// ---------------- gather + chequer perm + bn0 stats ----------------
__global__ void k_gather(const float* __restrict__ nf, const float* __restrict__ rf,
                         const int* __restrict__ sub, const int* __restrict__ rel) {
    int b = blockIdx.x;
    int t = threadIdx.x;   // 512
    float v = 0.f;
    if (t < NPIX) {
        int r = t / 20, c = t % 20;
        int idx = r * 10 + (c >> 1);
        int useB = (r + c) & 1;
        v = useB ? rf[rel[b] * DIM + idx]
                 : nf[(size_t)sub[b] * DIM + idx];
        g_X[b * NPIX + t] = v;
    }
    __shared__ float ss[512], sq[512];
    ss[t] = v; sq[t] = v * v;
    __syncthreads();
    for (int s = 256; s > 0; s >>= 1) {
        if (t < s) { ss[t] += ss[t + s]; sq[t] += sq[t + s]; }
        __syncthreads();
    }
    if (t == 0) { atomicAdd(&g_sums[0], ss[0]); atomicAdd(&g_sums[1], sq[0]); }
}

// ---------------- conv prologue ----------------
__device__ __forceinline__ void conv_prologue(int b, int t, float* xs, float* fs,
                                              const float* __restrict__ fw,
                                              const int* __restrict__ rel,
                                              const float* __restrict__ bn0g,
                                              const float* __restrict__ bn0b) {
    float invN = 1.0f / (float)(BATCH * NPIX);
    float m0 = g_sums[0] * invN;
    float v0 = g_sums[1] * invN - m0 * m0;
    float sc0 = bn0g[0] * rsqrtf(v0 + EPSF);
    float sh0 = bn0b[0] - sc0 * m0;
    for (int i = t; i < 484; i += 256) {
        int ph = i / 22, pw = i % 22;
        float val = 0.f;
        if (ph >= 1 && ph <= 20 && pw >= 1 && pw <= 20)
            val = sc0 * g_X[b * NPIX + (ph - 1) * 20 + (pw - 1)] + sh0;
        xs[i] = val;
    }
    int rb = rel[b];
    for (int i = t; i < OCH * 9; i += 256) fs[i] = fw[rb * (OCH * 9) + i];
}

__device__ __forceinline__ float conv_at(const float* xs, const float* f, int pix) {
    int h = pix / 20, w = pix % 20;
    const float* xp = &xs[h * 22 + w];
    return xp[0]  * f[0] + xp[1]  * f[1] + xp[2]  * f[2]
         + xp[22] * f[3] + xp[23] * f[4] + xp[24] * f[5]
         + xp[44] * f[6] + xp[45] * f[7] + xp[46] * f[8];
}

// ---------------- conv pass 1: channel stats ----------------
__global__ void k_conv_stats(const float* __restrict__ fw, const int* __restrict__ rel,
                             const float* __restrict__ bn0g, const float* __restrict__ bn0b) {
    int b = blockIdx.x;
    int t = threadIdx.x;
    __shared__ float xs[22 * 22];
    __shared__ float fs[OCH * 9];
    conv_prologue(b, t, xs, fs, fw, rel, bn0g, bn0b);
    __syncthreads();

    int oc = t >> 2, l4 = t & 3;
    float f[9];
#pragma unroll
    for (int j = 0; j < 9; j++) f[j] = fs[oc * 9 + j];

    float s1 = 0.f, s2 = 0.f;
#pragma unroll 4
    for (int s = 0; s < 100; s++) {
        int pix = l4 + 4 * s;
        float acc = conv_at(xs, f, pix);
        s1 += acc; s2 += acc * acc;
    }
    s1 += __shfl_down_sync(0xffffffffu, s1, 2, 4);
    s1 += __shfl_down_sync(0xffffffffu, s1, 1, 4);
    s2 += __shfl_down_sync(0xffffffffu, s2, 2, 4);
    s2 += __shfl_down_sync(0xffffffffu, s2, 1, 4);
    if (l4 == 0) { atomicAdd(&g_csum[oc], s1); atomicAdd(&g_csumsq[oc], s2); }
}

// ---------------- fc_w -> fp16 ----------------
__global__ void k_cvt_fcw(const float* __restrict__ fw) {
    int n = blockIdx.x;
    int t = threadIdx.x;
#pragma unroll 4
    for (int i = 0; i < 100; i++) {
        size_t idx = (size_t)n * FLATK + t + 256 * i;
        g_wh[idx] = __float2half_rn(fw[idx]);
    }
}

// ---------------- conv pass 2: BN-compose + BN + relu -> fp16, coalesced ----------------
__global__ void k_conv_fused(const float* __restrict__ fw, const int* __restrict__ rel,
                             const float* __restrict__ bn0g, const float* __restrict__ bn0b,
                             const float* __restrict__ cg, const float* __restrict__ b1g,
                             const float* __restrict__ b1b) {
    int b = blockIdx.x;
    int t = threadIdx.x;   // 256 = 8 warps
    __shared__ float xs[22 * 22];
    __shared__ float fs[OCH * 9];
    __shared__ float sSc[OCH], sSh[OCH];
    conv_prologue(b, t, xs, fs, fw, rel, bn0g, bn0b);
    if (t < OCH) {   // compose the two BN2d (redundant per block; cheap)
        float invN = 1.0f / (float)(BATCH * NPIX);
        float m = g_csum[t] * invN;
        float v = g_csumsq[t] * invN - m * m;
        float t1 = rsqrtf(v + EPSF);
        float var1 = cg[t] * cg[t] * v * t1 * t1;
        float t2 = rsqrtf(var1 + EPSF);
        float sc = b1g[t] * cg[t] * t1 * t2;
        sSc[t] = sc;
        sSh[t] = b1b[t] - sc * m;
    }
    __syncthreads();

    int lane = t & 31, w = t >> 5;   // warp w owns ocs [8w, 8w+8)
#pragma unroll
    for (int j = 0; j < 8; j++) {
        int oc = w * 8 + j;
        float f[9];
#pragma unroll
        for (int q = 0; q < 9; q++) f[q] = fs[oc * 9 + q];
        float sc = sSc[oc], sh = sSh[oc];
        size_t base = ((size_t)b * OCH + oc) * NPIX;
        __half2* dh = (__half2*)(g_yh + base);
        for (int i = lane; i < 200; i += 32) {
            float a0 = conv_at(xs, f, 2 * i);
            float a1 = conv_at(xs, f, 2 * i + 1);
            float z0 = sc * a0 + sh; z0 = z0 > 0.f ? z0 : 0.f;
            float z1 = sc * a1 + sh; z1 = z1 > 0.f ? z1 : 0.f;
            dh[i] = __halves2half2(__float2half_rn(z0), __float2half_rn(z1));
        }
    }
}

// ---------------- n_feats -> fp16 (padded) ----------------
__global__ void k_cvt_nf(const float* __restrict__ nf) {
    int n = blockIdx.x;      // 0..NENTP-1
    int k = threadIdx.x;     // 0..255
    float x = 0.f;
    if (n < NENT && k < DIM) x = nf[(size_t)n * DIM + k];
    g_bp[(size_t)n * KPASS + k] = __float2half_rn(x);
}

// ---------------- mma helpers ----------------
__device__ __forceinline__ uint32_t cvta_smem(const void* p) {
    uint32_t a;
    asm("{ .reg .u64 t; cvta.to.shared.u64 t, %1; cvt.u32.u64 %0, t; }" : "=r"(a) : "l"(p));
    return a;
}
__device__ __forceinline__ void cp16(uint32_t dst, const void* src, uint32_t sz) {
    asm volatile("cp.async.cg.shared.global [%0], [%1], 16, %2;"
                 :: "r"(dst), "l"(src), "r"(sz));
}
__device__ __forceinline__ void cp_commit() {
    asm volatile("cp.async.commit_group;");
}
template <int N>
__device__ __forceinline__ void cp_wait() {
    asm volatile("cp.async.wait_group %0;" :: "n"(N));
}
__device__ __forceinline__ void ldsm_x4(uint32_t& r0, uint32_t& r1, uint32_t& r2, uint32_t& r3,
                                        uint32_t addr) {
    asm volatile("ldmatrix.sync.aligned.m8n8.x4.shared.b16 {%0,%1,%2,%3}, [%4];"
                 : "=r"(r0), "=r"(r1), "=r"(r2), "=r"(r3) : "r"(addr));
}
__device__ __forceinline__ void mma_f16(float& d0, float& d1, float& d2, float& d3,
                                        uint32_t a0, uint32_t a1, uint32_t a2, uint32_t a3,
                                        uint32_t b0, uint32_t b1) {
    asm volatile("mma.sync.aligned.m16n8k16.row.col.f32.f16.f16.f32 "
                 "{%0,%1,%2,%3}, {%4,%5,%6,%7}, {%8,%9}, {%0,%1,%2,%3};"
                 : "+f"(d0), "+f"(d1), "+f"(d2), "+f"(d3)
                 : "r"(a0), "r"(a1), "r"(a2), "r"(a3), "r"(b0), "r"(b1));
}

// ---------------- FC GEMM: CTA 128Mx256N, 512 threads, single pass ----------------
#define FC_ASZ 16384
#define FC_BSZ 32768
#define FC_STG (FC_ASZ + FC_BSZ)    // 48KB per stage

__global__ __launch_bounds__(512, 1) void k_fc_mma() {
    extern __shared__ __align__(1024) unsigned char dsm[];
    int t = threadIdx.x;
    int lane = t & 31, wid = t >> 5;     // 16 warps
    int wm = (wid >> 3) * 64;            // 0 / 64
    int wn = (wid & 7) * 32;             // 0..224
    int m0 = blockIdx.y * 128;
    int ks = blockIdx.z;
    size_t kbase = (size_t)ks * KSEG;

    uint32_t smemBase = cvta_smem(dsm);

    int rowA[2]; uint32_t soA[2]; int segA[2];
#pragma unroll
    for (int r = 0; r < 2; r++) {
        int e = t + 512 * r;
        rowA[r] = e >> 3; segA[r] = e & 7;
        soA[r] = (uint32_t)rowA[r] * 128 + (uint32_t)((segA[r] ^ (rowA[r] & 7)) << 4);
    }
    int rowB[4]; uint32_t soB[4]; int segB[4];
#pragma unroll
    for (int r = 0; r < 4; r++) {
        int e = t + 512 * r;
        rowB[r] = e >> 3; segB[r] = e & 7;
        soB[r] = (uint32_t)rowB[r] * 128 + (uint32_t)((segB[r] ^ (rowB[r] & 7)) << 4);
    }

    int grp = lane >> 3, li = lane & 7;
    int roffA = ((grp & 1) << 3) + li;
    int cgA = grp >> 1;
    int noffB = ((grp >> 1) << 3) + li;
    int cgB = grp & 1;

    float acc[4][4][4];
#pragma unroll
    for (int a = 0; a < 4; a++)
#pragma unroll
        for (int b = 0; b < 4; b++)
#pragma unroll
            for (int c = 0; c < 4; c++) acc[a][b][c] = 0.f;

    auto issue = [&](int idx) {
        size_t koff = kbase + (size_t)idx * 64;
        uint32_t base = smemBase + (uint32_t)(idx & 1) * FC_STG;
#pragma unroll
        for (int r = 0; r < 2; r++) {
            size_t ga = (size_t)(m0 + rowA[r]) * FLATK + koff + segA[r] * 8;
            cp16(base + soA[r], g_yh + ga, 16);
        }
#pragma unroll
        for (int r = 0; r < 4; r++) {
            int nrow = rowB[r];
            int ok = nrow < DIM;
            size_t gb = (size_t)(ok ? nrow : 0) * FLATK + koff + segB[r] * 8;
            cp16(base + FC_ASZ + soB[r], g_wh + gb, ok ? 16u : 0u);
        }
        cp_commit();
    };

    issue(0);
    for (int ch = 0; ch < FC_CHUNKS; ch++) {
        if (ch < FC_CHUNKS - 1) { issue(ch + 1); cp_wait<1>(); }
        else cp_wait<0>();
        __syncthreads();
        uint32_t baseA = smemBase + (uint32_t)(ch & 1) * FC_STG;
        uint32_t baseB = baseA + FC_ASZ;
#pragma unroll
        for (int kf = 0; kf < 4; kf++) {
            uint32_t a[4][4];
#pragma unroll
            for (int mf = 0; mf < 4; mf++) {
                int row = wm + mf * 16 + roffA;
                uint32_t addr = baseA + (uint32_t)row * 128
                              + (uint32_t)(((kf * 2 + cgA) ^ li) << 4);
                ldsm_x4(a[mf][0], a[mf][1], a[mf][2], a[mf][3], addr);
            }
            uint32_t b[4][2];
#pragma unroll
            for (int nf2 = 0; nf2 < 2; nf2++) {
                int row = wn + nf2 * 16 + noffB;
                uint32_t addr = baseB + (uint32_t)row * 128
                              + (uint32_t)(((kf * 2 + cgB) ^ li) << 4);
                ldsm_x4(b[nf2 * 2][0], b[nf2 * 2][1], b[nf2 * 2 + 1][0], b[nf2 * 2 + 1][1], addr);
            }
#pragma unroll
            for (int mf = 0; mf < 4; mf++)
#pragma unroll
                for (int nf = 0; nf < 4; nf++)
                    mma_f16(acc[mf][nf][0], acc[mf][nf][1], acc[mf][nf][2], acc[mf][nf][3],
                            a[mf][0], a[mf][1], a[mf][2], a[mf][3],
                            b[nf][0], b[nf][1]);
        }
        __syncthreads();
    }

    int g = lane >> 2, c = lane & 3;
    float* hp = g_hp + (size_t)ks * BATCH * NPADFC;
#pragma unroll
    for (int mf = 0; mf < 4; mf++) {
#pragma unroll
        for (int nf = 0; nf < 4; nf++) {
            int n = wn + nf * 8 + c * 2;
            int m = m0 + wm + mf * 16 + g;
            float2 v0 = {acc[mf][nf][0], acc[mf][nf][1]};
            *(float2*)(hp + (size_t)m * NPADFC + n) = v0;
            float2 v1 = {acc[mf][nf][2], acc[mf][nf][3]};
            *(float2*)(hp + (size_t)(m + 8) * NPADFC + n) = v1;
        }
    }
}

// ---------------- reduce fc partials + bias ----------------
__global__ void k_fcred(const float* __restrict__ fb) {
    int m = blockIdx.x;
    int t = threadIdx.x;
    if (t >= DIM) return;
    float s = fb[t];
#pragma unroll
    for (int z = 0; z < KSPLIT; z++)
        s += g_hp[((size_t)z * BATCH + m) * NPADFC + t];
    g_H[m * DIM + t] = s;
}

// ---------------- bn1d + relu -> A (hi, padded) ----------------
__global__ void k_bn1d(const float* __restrict__ b2g, const float* __restrict__ b2b) {
    int d = blockIdx.x;     // 0..255
    int t = threadIdx.x;    // 256
    if (d >= DIM) {
        __half z16 = __float2half_rn(0.f);
        for (int i = t; i < BATCH; i += 256)
            g_ap[(size_t)i * KPASS + d] = z16;
        return;
    }
    float vals[8];
    float s1 = 0.f, s2 = 0.f;
#pragma unroll
    for (int i = 0; i < 8; i++) {
        float h = g_H[(t + 256 * i) * DIM + d];
        vals[i] = h; s1 += h; s2 += h * h;
    }
    __shared__ float ss[256], sq[256];
    ss[t] = s1; sq[t] = s2;
    __syncthreads();
    for (int s = 128; s > 0; s >>= 1) {
        if (t < s) { ss[t] += ss[t + s]; sq[t] += sq[t + s]; }
        __syncthreads();
    }
    __shared__ float ssc, ssh;
    if (t == 0) {
        float m = ss[0] / (float)BATCH;
        float v = sq[0] / (float)BATCH - m * m;
        float sc = b2g[d] * rsqrtf(v + EPSF);
        ssc = sc; ssh = b2b[d] - sc * m;
    }
    __syncthreads();
    float sc = ssc, sh = ssh;
#pragma unroll
    for (int i = 0; i < 8; i++) {
        float z = sc * vals[i] + sh;
        z = z > 0.f ? z : 0.f;
        g_ap[(size_t)(t + 256 * i) * KPASS + d] = __float2half_rn(z);
    }
}

// ---------------- scoring GEMM: fp16, effective K=208 ----------------
#define STAGE_BYTES 32768

__global__ __launch_bounds__(256, 2) void k_out_mma(const float* __restrict__ eb,
                                                    float* __restrict__ out) {
    extern __shared__ __align__(1024) unsigned char dsm[];
    int t = threadIdx.x;
    int lane = t & 31, wid = t >> 5;
    int wm = (wid >> 2) * 64;
    int wn = (wid & 3) * 32;
    int m0 = blockIdx.x * 128;
    int n0 = blockIdx.y * NTILE;

    uint32_t smemBase = cvta_smem(dsm);

    int rowL[4]; uint32_t soL[4]; int segL[4];
#pragma unroll
    for (int r = 0; r < 4; r++) {
        int e = t + 256 * r;
        rowL[r] = e >> 3;
        segL[r] = e & 7;
        soL[r] = (uint32_t)rowL[r] * 128 + (uint32_t)((segL[r] ^ (rowL[r] & 7)) << 4);
    }
    const __half* pA = g_ap + (size_t)m0 * KPASS;
    const __half* pB = g_bp + (size_t)n0 * KPASS;

    int grp = lane >> 3, li = lane & 7;
    int roffA = ((grp & 1) << 3) + li;
    int cgA = grp >> 1;
    int noffB = ((grp >> 1) << 3) + li;
    int cgB = grp & 1;

    float acc[4][4][4];
#pragma unroll
    for (int a = 0; a < 4; a++)
#pragma unroll
        for (int b = 0; b < 4; b++)
#pragma unroll
            for (int c = 0; c < 4; c++) acc[a][b][c] = 0.f;

    auto issue = [&](int ch) {
        uint32_t base = smemBase + (uint32_t)(ch & 1) * STAGE_BYTES;
#pragma unroll
        for (int r = 0; r < 4; r++) {
            size_t go = (size_t)rowL[r] * KPASS + ch * 64 + segL[r] * 8;
            cp16(base + soL[r], pA + go, 16);
            cp16(base + 16384 + soL[r], pB + go, 16);
        }
        cp_commit();
    };

    issue(0);
    for (int ch = 0; ch < 4; ch++) {
        if (ch < 3) { issue(ch + 1); cp_wait<1>(); }
        else cp_wait<0>();
        __syncthreads();
        uint32_t baseA = smemBase + (uint32_t)(ch & 1) * STAGE_BYTES;
        uint32_t baseB = baseA + 16384;
        int nkf = (ch == 3) ? 1 : 4;   // K = 3*64 + 16 = 208 >= 200
        for (int kf = 0; kf < nkf; kf++) {
            uint32_t a[4][4];
#pragma unroll
            for (int mf = 0; mf < 4; mf++) {
                int row = wm + mf * 16 + roffA;
                uint32_t addr = baseA + (uint32_t)row * 128
                              + (uint32_t)(((kf * 2 + cgA) ^ li) << 4);
                ldsm_x4(a[mf][0], a[mf][1], a[mf][2], a[mf][3], addr);
            }
            uint32_t b[4][2];
#pragma unroll
            for (int nf2 = 0; nf2 < 2; nf2++) {
                int row = wn + nf2 * 16 + noffB;
                uint32_t addr = baseB + (uint32_t)row * 128
                              + (uint32_t)(((kf * 2 + cgB) ^ li) << 4);
                ldsm_x4(b[nf2 * 2][0], b[nf2 * 2][1], b[nf2 * 2 + 1][0], b[nf2 * 2 + 1][1], addr);
            }
#pragma unroll
            for (int mf = 0; mf < 4; mf++)
#pragma unroll
                for (int nf = 0; nf < 4; nf++)
                    mma_f16(acc[mf][nf][0], acc[mf][nf][1], acc[mf][nf][2], acc[mf][nf][3],
                            a[mf][0], a[mf][1], a[mf][2], a[mf][3],
                            b[nf][0], b[nf][1]);
        }
        __syncthreads();
    }

    int g = lane >> 2, c = lane & 3;
#pragma unroll
    for (int mf = 0; mf < 4; mf++) {
#pragma unroll
        for (int nf = 0; nf < 4; nf++) {
            int n = n0 + wn + nf * 8 + c * 2;
            if (n < NENT) {
                float2 bias = *(const float2*)(eb + n);
                int m = m0 + wm + mf * 16 + g;
                float2 v0 = {acc[mf][nf][0] + bias.x, acc[mf][nf][1] + bias.y};
                *(float2*)(out + (size_t)m * NENT + n) = v0;
                float2 v1 = {acc[mf][nf][2] + bias.x, acc[mf][nf][3] + bias.y};
                *(float2*)(out + (size_t)(m + 8) * NENT + n) = v1;
            }
        }
    }
}

// ---------------- launch ----------------
extern "C" void kernel_launch(void* const* d_in, const int* in_sizes, int n_in,
                              void* d_out, int out_size) {
    const float* nf   = (const float*)d_in[0];
    const float* rf   = (const float*)d_in[1];
    const float* fw   = (const float*)d_in[2];
    const float* bn0g = (const float*)d_in[3];
    const float* bn0b = (const float*)d_in[4];
    const float* cbng = (const float*)d_in[5];
    const float* cbnb = (const float*)d_in[6];
    const float* bn1g = (const float*)d_in[7];
    const float* bn1b = (const float*)d_in[8];
    const float* fcw  = (const float*)d_in[9];
    const float* fcb  = (const float*)d_in[10];
    const float* bn2g = (const float*)d_in[11];
    const float* bn2b = (const float*)d_in[12];
    const float* eb   = (const float*)d_in[13];
    const int*   sub  = (const int*)d_in[14];
    const int*   rel  = (const int*)d_in[15];
    float* out = (float*)d_out;

    cudaFuncSetAttribute(k_out_mma, cudaFuncAttributeMaxDynamicSharedMemorySize, 2 * STAGE_BYTES);
    cudaFuncSetAttribute(k_fc_mma, cudaFuncAttributeMaxDynamicSharedMemorySize, 2 * FC_STG);

    k_init<<<1, 256>>>();
    k_gather<<<BATCH, 512>>>(nf, rf, sub, rel);
    k_conv_stats<<<BATCH, 256>>>(fw, rel, bn0g, bn0b);
    k_cvt_fcw<<<DIM, 256>>>(fcw);
    k_conv_fused<<<BATCH, 256>>>(fw, rel, bn0g, bn0b, cbng, bn1g, bn1b);
    k_fc_mma<<<dim3(1, 16, KSPLIT), 512, 2 * FC_STG>>>();
    k_cvt_nf<<<NENTP, 256>>>(nf);
    k_fcred<<<BATCH, 256>>>(fcb);
    k_bn1d<<<KPASS, 256>>>(bn2g, bn2b);
    k_out_mma<<<dim3(16, NTILES), 256, 2 * STAGE_BYTES>>>(eb, out);
}

// round 14
// speedup vs baseline: 1.6904x; 1.0684x over previous
#include <cuda_runtime.h>
#include <cuda_fp16.h>
#include <math.h>
#include <stdint.h>

#define BATCH   2048
#define DIM     200
#define OCH     64
#define NPIX    400          // 20x20
#define FLATK   25600        // 64*400
#define NENT    50000
#define EPSF    1e-5f

#define KPASS   256          // padded K storage (200 -> 256)
#define NTILE   128
#define NTILES  391
#define NENTP   (NTILES*NTILE)   // 50048
#define KSPLIT  8
#define KSEG    (FLATK/KSPLIT)   // 3200
#define NPADFC  256
#define FC_CHUNKS 50         // single fp16 pass

// ---------------- scratch ----------------
__device__ float g_X[BATCH * NPIX];
__device__ float g_H[BATCH * DIM];
__device__ float g_sums[2];
__device__ float g_csum[OCH];
__device__ float g_csumsq[OCH];
__device__ __half g_ap[(size_t)BATCH * KPASS];      // scoring A (hi) 1MB
__device__ __half g_bp[(size_t)NENTP * KPASS];      // scoring B (hi) 25.6MB
__device__ __half g_yh[(size_t)BATCH * FLATK];      // fc A 105MB
__device__ __half g_wh[(size_t)DIM * FLATK];        // fc W 10.3MB
__device__ float g_hp[(size_t)KSPLIT * BATCH * NPADFC];

// ---------------- init ----------------
__global__ void k_init() {
    int t = threadIdx.x;
    if (t < 2) g_sums[t] = 0.f;
    if (t < OCH) { g_csum[t] = 0.f; g_csumsq[t] = 0.f; }
}

// ---------------- gather + chequer perm + bn0 stats ----------------
__global__ void k_gather(const float* __restrict__ nf, const float* __restrict__ rf,
                         const int* __restrict__ sub, const int* __restrict__ rel) {
    int b = blockIdx.x;
    int t = threadIdx.x;   // 512
    float v = 0.f;
    if (t < NPIX) {
        int r = t / 20, c = t % 20;
        int idx = r * 10 + (c >> 1);
        int useB = (r + c) & 1;
        v = useB ? rf[rel[b] * DIM + idx]
                 : nf[(size_t)sub[b] * DIM + idx];
        g_X[b * NPIX + t] = v;
    }
    __shared__ float ss[512], sq[512];
    ss[t] = v; sq[t] = v * v;
    __syncthreads();
    for (int s = 256; s > 0; s >>= 1) {
        if (t < s) { ss[t] += ss[t + s]; sq[t] += sq[t + s]; }
        __syncthreads();
    }
    if (t == 0) { atomicAdd(&g_sums[0], ss[0]); atomicAdd(&g_sums[1], sq[0]); }
}

// ---------------- conv prologue ----------------
__device__ __forceinline__ void conv_prologue(int b, int t, float* xs, float* fs,
                                              const float* __restrict__ fw,
                                              const int* __restrict__ rel,
                                              const float* __restrict__ bn0g,
                                              const float* __restrict__ bn0b) {
    float invN = 1.0f / (float)(BATCH * NPIX);
    float m0 = g_sums[0] * invN;
    float v0 = g_sums[1] * invN - m0 * m0;
    float sc0 = bn0g[0] * rsqrtf(v0 + EPSF);
    float sh0 = bn0b[0] - sc0 * m0;
    for (int i = t; i < 484; i += 256) {
        int ph = i / 22, pw = i % 22;
        float val = 0.f;
        if (ph >= 1 && ph <= 20 && pw >= 1 && pw <= 20)
            val = sc0 * g_X[b * NPIX + (ph - 1) * 20 + (pw - 1)] + sh0;
        xs[i] = val;
    }
    int rb = rel[b];
    for (int i = t; i < OCH * 9; i += 256) fs[i] = fw[rb * (OCH * 9) + i];
}

__device__ __forceinline__ float conv_at(const float* xs, const float* f, int pix) {
    int h = pix / 20, w = pix % 20;
    const float* xp = &xs[h * 22 + w];
    return xp[0]  * f[0] + xp[1]  * f[1] + xp[2]  * f[2]
         + xp[22] * f[3] + xp[23] * f[4] + xp[24] * f[5]
         + xp[44] * f[6] + xp[45] * f[7] + xp[46] * f[8];
}

// ---------------- conv pass 1: channel stats ----------------
__global__ void k_conv_stats(const float* __restrict__ fw, const int* __restrict__ rel,
                             const float* __restrict__ bn0g, const float* __restrict__ bn0b) {
    int b = blockIdx.x;
    int t = threadIdx.x;
    __shared__ float xs[22 * 22];
    __shared__ float fs[OCH * 9];
    conv_prologue(b, t, xs, fs, fw, rel, bn0g, bn0b);
    __syncthreads();

    int oc = t >> 2, l4 = t & 3;
    float f[9];
#pragma unroll
    for (int j = 0; j < 9; j++) f[j] = fs[oc * 9 + j];

    float s1 = 0.f, s2 = 0.f;
#pragma unroll 4
    for (int s = 0; s < 100; s++) {
        int pix = l4 + 4 * s;
        float acc = conv_at(xs, f, pix);
        s1 += acc; s2 += acc * acc;
    }
    s1 += __shfl_down_sync(0xffffffffu, s1, 2, 4);
    s1 += __shfl_down_sync(0xffffffffu, s1, 1, 4);
    s2 += __shfl_down_sync(0xffffffffu, s2, 2, 4);
    s2 += __shfl_down_sync(0xffffffffu, s2, 1, 4);
    if (l4 == 0) { atomicAdd(&g_csum[oc], s1); atomicAdd(&g_csumsq[oc], s2); }
}

// ---------------- fc_w -> fp16 (vectorized) ----------------
__global__ void k_cvt_fcw(const float* __restrict__ fw) {
    int i = blockIdx.x * 256 + threadIdx.x;   // 5120000/4 = 1,280,000 float4s
    if (i < 1280000) {
        float4 v = *(const float4*)(fw + (size_t)i * 4);
        __half2* dst = (__half2*)g_wh + (size_t)i * 2;
        dst[0] = __floats2half2_rn(v.x, v.y);
        dst[1] = __floats2half2_rn(v.z, v.w);
    }
}

// ---------------- conv pass 2: BN-compose + BN + relu -> fp16, coalesced ----------------
__global__ void k_conv_fused(const float* __restrict__ fw, const int* __restrict__ rel,
                             const float* __restrict__ bn0g, const float* __restrict__ bn0b,
                             const float* __restrict__ cg, const float* __restrict__ b1g,
                             const float* __restrict__ b1b) {
    int b = blockIdx.x;
    int t = threadIdx.x;   // 256 = 8 warps
    __shared__ float xs[22 * 22];
    __shared__ float fs[OCH * 9];
    __shared__ float sSc[OCH], sSh[OCH];
    conv_prologue(b, t, xs, fs, fw, rel, bn0g, bn0b);
    if (t < OCH) {   // compose the two BN2d (redundant per block; cheap)
        float invN = 1.0f / (float)(BATCH * NPIX);
        float m = g_csum[t] * invN;
        float v = g_csumsq[t] * invN - m * m;
        float t1 = rsqrtf(v + EPSF);
        float var1 = cg[t] * cg[t] * v * t1 * t1;
        float t2 = rsqrtf(var1 + EPSF);
        float sc = b1g[t] * cg[t] * t1 * t2;
        sSc[t] = sc;
        sSh[t] = b1b[t] - sc * m;
    }
    __syncthreads();

    int lane = t & 31, w = t >> 5;   // warp w owns ocs [8w, 8w+8)
#pragma unroll
    for (int j = 0; j < 8; j++) {
        int oc = w * 8 + j;
        float f[9];
#pragma unroll
        for (int q = 0; q < 9; q++) f[q] = fs[oc * 9 + q];
        float sc = sSc[oc], sh = sSh[oc];
        size_t base = ((size_t)b * OCH + oc) * NPIX;
        __half2* dh = (__half2*)(g_yh + base);
        for (int i = lane; i < 200; i += 32) {
            float a0 = conv_at(xs, f, 2 * i);
            float a1 = conv_at(xs, f, 2 * i + 1);
            float z0 = sc * a0 + sh; z0 = z0 > 0.f ? z0 : 0.f;
            float z1 = sc * a1 + sh; z1 = z1 > 0.f ? z1 : 0.f;
            dh[i] = __halves2half2(__float2half_rn(z0), __float2half_rn(z1));
        }
    }
}

// ---------------- n_feats -> fp16 (padded, vectorized: 4 rows/block) ----------------
__global__ void k_cvt_nf(const float* __restrict__ nf) {
    int n = blockIdx.x * 4 + (threadIdx.x >> 6);   // row
    int s = threadIdx.x & 63;                      // 4 k's per slot
    __half2 h0 = __floats2half2_rn(0.f, 0.f), h1 = h0;
    if (n < NENT && 4 * s < DIM) {
        float4 v = *(const float4*)(nf + (size_t)n * DIM + 4 * s);
        h0 = __floats2half2_rn(v.x, v.y);
        h1 = __floats2half2_rn(v.z, v.w);
    }
    __half2* dst = (__half2*)g_bp + (size_t)n * (KPASS / 2) + 2 * s;
    dst[0] = h0;
    dst[1] = h1;
}

// ---------------- mma helpers ----------------
__device__ __forceinline__ uint32_t cvta_smem(const void* p) {
    uint32_t a;
    asm("{ .reg .u64 t; cvta.to.shared.u64 t, %1; cvt.u32.u64 %0, t; }" : "=r"(a) : "l"(p));
    return a;
}
__device__ __forceinline__ void cp16(uint32_t dst, const void* src, uint32_t sz) {
    asm volatile("cp.async.cg.shared.global [%0], [%1], 16, %2;"
                 :: "r"(dst), "l"(src), "r"(sz));
}
__device__ __forceinline__ void cp_commit() {
    asm volatile("cp.async.commit_group;");
}
template <int N>
__device__ __forceinline__ void cp_wait() {
    asm volatile("cp.async.wait_group %0;" :: "n"(N));
}
__device__ __forceinline__ void ldsm_x4(uint32_t& r0, uint32_t& r1, uint32_t& r2, uint32_t& r3,
                                        uint32_t addr) {
    asm volatile("ldmatrix.sync.aligned.m8n8.x4.shared.b16 {%0,%1,%2,%3}, [%4];"
                 : "=r"(r0), "=r"(r1), "=r"(r2), "=r"(r3) : "r"(addr));
}
__device__ __forceinline__ void mma_f16(float& d0, float& d1, float& d2, float& d3,
                                        uint32_t a0, uint32_t a1, uint32_t a2, uint32_t a3,
                                        uint32_t b0, uint32_t b1) {
    asm volatile("mma.sync.aligned.m16n8k16.row.col.f32.f16.f16.f32 "
                 "{%0,%1,%2,%3}, {%4,%5,%6,%7}, {%8,%9}, {%0,%1,%2,%3};"
                 : "+f"(d0), "+f"(d1), "+f"(d2), "+f"(d3)
                 : "r"(a0), "r"(a1), "r"(a2), "r"(a3), "r"(b0), "r"(b1));
}

// ---------------- FC GEMM: CTA 128Mx256N, 512 threads, single pass ----------------
#define FC_ASZ 16384
#define FC_BSZ 32768
#define FC_STG (FC_ASZ + FC_BSZ)    // 48KB per stage

__global__ __launch_bounds__(512, 1) void k_fc_mma() {
    extern __shared__ __align__(1024) unsigned char dsm[];
    int t = threadIdx.x;
    int lane = t & 31, wid = t >> 5;     // 16 warps
    int wm = (wid >> 3) * 64;            // 0 / 64
    int wn = (wid & 7) * 32;             // 0..224
    int m0 = blockIdx.y * 128;
    int ks = blockIdx.z;
    size_t kbase = (size_t)ks * KSEG;

    uint32_t smemBase = cvta_smem(dsm);

    int rowA[2]; uint32_t soA[2]; int segA[2];
#pragma unroll
    for (int r = 0; r < 2; r++) {
        int e = t + 512 * r;
        rowA[r] = e >> 3; segA[r] = e & 7;
        soA[r] = (uint32_t)rowA[r] * 128 + (uint32_t)((segA[r] ^ (rowA[r] & 7)) << 4);
    }
    int rowB[4]; uint32_t soB[4]; int segB[4];
#pragma unroll
    for (int r = 0; r < 4; r++) {
        int e = t + 512 * r;
        rowB[r] = e >> 3; segB[r] = e & 7;
        soB[r] = (uint32_t)rowB[r] * 128 + (uint32_t)((segB[r] ^ (rowB[r] & 7)) << 4);
    }

    int grp = lane >> 3, li = lane & 7;
    int roffA = ((grp & 1) << 3) + li;
    int cgA = grp >> 1;
    int noffB = ((grp >> 1) << 3) + li;
    int cgB = grp & 1;

    float acc[4][4][4];
#pragma unroll
    for (int a = 0; a < 4; a++)
#pragma unroll
        for (int b = 0; b < 4; b++)
#pragma unroll
            for (int c = 0; c < 4; c++) acc[a][b][c] = 0.f;

    auto issue = [&](int idx) {
        size_t koff = kbase + (size_t)idx * 64;
        uint32_t base = smemBase + (uint32_t)(idx & 1) * FC_STG;
#pragma unroll
        for (int r = 0; r < 2; r++) {
            size_t ga = (size_t)(m0 + rowA[r]) * FLATK + koff + segA[r] * 8;
            cp16(base + soA[r], g_yh + ga, 16);
        }
#pragma unroll
        for (int r = 0; r < 4; r++) {
            int nrow = rowB[r];
            int ok = nrow < DIM;
            size_t gb = (size_t)(ok ? nrow : 0) * FLATK + koff + segB[r] * 8;
            cp16(base + FC_ASZ + soB[r], g_wh + gb, ok ? 16u : 0u);
        }
        cp_commit();
    };

    issue(0);
    for (int ch = 0; ch < FC_CHUNKS; ch++) {
        if (ch < FC_CHUNKS - 1) { issue(ch + 1); cp_wait<1>(); }
        else cp_wait<0>();
        __syncthreads();
        uint32_t baseA = smemBase + (uint32_t)(ch & 1) * FC_STG;
        uint32_t baseB = baseA + FC_ASZ;
#pragma unroll
        for (int kf = 0; kf < 4; kf++) {
            uint32_t a[4][4];
#pragma unroll
            for (int mf = 0; mf < 4; mf++) {
                int row = wm + mf * 16 + roffA;
                uint32_t addr = baseA + (uint32_t)row * 128
                              + (uint32_t)(((kf * 2 + cgA) ^ li) << 4);
                ldsm_x4(a[mf][0], a[mf][1], a[mf][2], a[mf][3], addr);
            }
            uint32_t b[4][2];
#pragma unroll
            for (int nf2 = 0; nf2 < 2; nf2++) {
                int row = wn + nf2 * 16 + noffB;
                uint32_t addr = baseB + (uint32_t)row * 128
                              + (uint32_t)(((kf * 2 + cgB) ^ li) << 4);
                ldsm_x4(b[nf2 * 2][0], b[nf2 * 2][1], b[nf2 * 2 + 1][0], b[nf2 * 2 + 1][1], addr);
            }
#pragma unroll
            for (int mf = 0; mf < 4; mf++)
#pragma unroll
                for (int nf = 0; nf < 4; nf++)
                    mma_f16(acc[mf][nf][0], acc[mf][nf][1], acc[mf][nf][2], acc[mf][nf][3],
                            a[mf][0], a[mf][1], a[mf][2], a[mf][3],
                            b[nf][0], b[nf][1]);
        }
        __syncthreads();
    }

    int g = lane >> 2, c = lane & 3;
    float* hp = g_hp + (size_t)ks * BATCH * NPADFC;
#pragma unroll
    for (int mf = 0; mf < 4; mf++) {
#pragma unroll
        for (int nf = 0; nf < 4; nf++) {
            int n = wn + nf * 8 + c * 2;
            int m = m0 + wm + mf * 16 + g;
            float2 v0 = {acc[mf][nf][0], acc[mf][nf][1]};
            *(float2*)(hp + (size_t)m * NPADFC + n) = v0;
            float2 v1 = {acc[mf][nf][2], acc[mf][nf][3]};
            *(float2*)(hp + (size_t)(m + 8) * NPADFC + n) = v1;
        }
    }
}

// ---------------- reduce fc partials + bias ----------------
__global__ void k_fcred(const float* __restrict__ fb) {
    int m = blockIdx.x;
    int t = threadIdx.x;
    if (t >= DIM) return;
    float s = fb[t];
#pragma unroll
    for (int z = 0; z < KSPLIT; z++)
        s += g_hp[((size_t)z * BATCH + m) * NPADFC + t];
    g_H[m * DIM + t] = s;
}

// ---------------- bn1d + relu -> A (hi, padded) ----------------
__global__ void k_bn1d(const float* __restrict__ b2g, const float* __restrict__ b2b) {
    int d = blockIdx.x;     // 0..255
    int t = threadIdx.x;    // 256
    if (d >= DIM) {
        __half z16 = __float2half_rn(0.f);
        for (int i = t; i < BATCH; i += 256)
            g_ap[(size_t)i * KPASS + d] = z16;
        return;
    }
    float vals[8];
    float s1 = 0.f, s2 = 0.f;
#pragma unroll
    for (int i = 0; i < 8; i++) {
        float h = g_H[(t + 256 * i) * DIM + d];
        vals[i] = h; s1 += h; s2 += h * h;
    }
    __shared__ float ss[256], sq[256];
    ss[t] = s1; sq[t] = s2;
    __syncthreads();
    for (int s = 128; s > 0; s >>= 1) {
        if (t < s) { ss[t] += ss[t + s]; sq[t] += sq[t + s]; }
        __syncthreads();
    }
    __shared__ float ssc, ssh;
    if (t == 0) {
        float m = ss[0] / (float)BATCH;
        float v = sq[0] / (float)BATCH - m * m;
        float sc = b2g[d] * rsqrtf(v + EPSF);
        ssc = sc; ssh = b2b[d] - sc * m;
    }
    __syncthreads();
    float sc = ssc, sh = ssh;
#pragma unroll
    for (int i = 0; i < 8; i++) {
        float z = sc * vals[i] + sh;
        z = z > 0.f ? z : 0.f;
        g_ap[(size_t)(t + 256 * i) * KPASS + d] = __float2half_rn(z);
    }
}

// ---------------- scoring GEMM: fp16, effective K=208 ----------------
#define STAGE_BYTES 32768

__global__ __launch_bounds__(256, 2) void k_out_mma(const float* __restrict__ eb,
                                                    float* __restrict__ out) {
    extern __shared__ __align__(1024) unsigned char dsm[];
    int t = threadIdx.x;
    int lane = t & 31, wid = t >> 5;
    int wm = (wid >> 2) * 64;
    int wn = (wid & 3) * 32;
    int m0 = blockIdx.x * 128;
    int n0 = blockIdx.y * NTILE;

    uint32_t smemBase = cvta_smem(dsm);

    int rowL[4]; uint32_t soL[4]; int segL[4];
#pragma unroll
    for (int r = 0; r < 4; r++) {
        int e = t + 256 * r;
        rowL[r] = e >> 3;
        segL[r] = e & 7;
        soL[r] = (uint32_t)rowL[r] * 128 + (uint32_t)((segL[r] ^ (rowL[r] & 7)) << 4);
    }
    const __half* pA = g_ap + (size_t)m0 * KPASS;
    const __half* pB = g_bp + (size_t)n0 * KPASS;

    int grp = lane >> 3, li = lane & 7;
    int roffA = ((grp & 1) << 3) + li;
    int cgA = grp >> 1;
    int noffB = ((grp >> 1) << 3) + li;
    int cgB = grp & 1;

    float acc[4][4][4];
#pragma unroll
    for (int a = 0; a < 4; a++)
#pragma unroll
        for (int b = 0; b < 4; b++)
#pragma unroll
            for (int c = 0; c < 4; c++) acc[a][b][c] = 0.f;

    auto issue = [&](int ch) {
        uint32_t base = smemBase + (uint32_t)(ch & 1) * STAGE_BYTES;
#pragma unroll
        for (int r = 0; r < 4; r++) {
            size_t go = (size_t)rowL[r] * KPASS + ch * 64 + segL[r] * 8;
            cp16(base + soL[r], pA + go, 16);
            cp16(base + 16384 + soL[r], pB + go, 16);
        }
        cp_commit();
    };

    issue(0);
    for (int ch = 0; ch < 4; ch++) {
        if (ch < 3) { issue(ch + 1); cp_wait<1>(); }
        else cp_wait<0>();
        __syncthreads();
        uint32_t baseA = smemBase + (uint32_t)(ch & 1) * STAGE_BYTES;
        uint32_t baseB = baseA + 16384;
        int nkf = (ch == 3) ? 1 : 4;   // K = 3*64 + 16 = 208 >= 200
        for (int kf = 0; kf < nkf; kf++) {
            uint32_t a[4][4];
#pragma unroll
            for (int mf = 0; mf < 4; mf++) {
                int row = wm + mf * 16 + roffA;
                uint32_t addr = baseA + (uint32_t)row * 128
                              + (uint32_t)(((kf * 2 + cgA) ^ li) << 4);
                ldsm_x4(a[mf][0], a[mf][1], a[mf][2], a[mf][3], addr);
            }
            uint32_t b[4][2];
#pragma unroll
            for (int nf2 = 0; nf2 < 2; nf2++) {
                int row = wn + nf2 * 16 + noffB;
                uint32_t addr = baseB + (uint32_t)row * 128
                              + (uint32_t)(((kf * 2 + cgB) ^ li) << 4);
                ldsm_x4(b[nf2 * 2][0], b[nf2 * 2][1], b[nf2 * 2 + 1][0], b[nf2 * 2 + 1][1], addr);
            }
#pragma unroll
            for (int mf = 0; mf < 4; mf++)
#pragma unroll
                for (int nf = 0; nf < 4; nf++)
                    mma_f16(acc[mf][nf][0], acc[mf][nf][1], acc[mf][nf][2], acc[mf][nf][3],
                            a[mf][0], a[mf][1], a[mf][2], a[mf][3],
                            b[nf][0], b[nf][1]);
        }
        __syncthreads();
    }

    int g = lane >> 2, c = lane & 3;
#pragma unroll
    for (int mf = 0; mf < 4; mf++) {
#pragma unroll
        for (int nf = 0; nf < 4; nf++) {
            int n = n0 + wn + nf * 8 + c * 2;
            if (n < NENT) {
                float2 bias = *(const float2*)(eb + n);
                int m = m0 + wm + mf * 16 + g;
                float2 v0 = {acc[mf][nf][0] + bias.x, acc[mf][nf][1] + bias.y};
                *(float2*)(out + (size_t)m * NENT + n) = v0;
                float2 v1 = {acc[mf][nf][2] + bias.x, acc[mf][nf][3] + bias.y};
                *(float2*)(out + (size_t)(m + 8) * NENT + n) = v1;
            }
        }
    }
}

// ---------------- launch ----------------
extern "C" void kernel_launch(void* const* d_in, const int* in_sizes, int n_in,
                              void* d_out, int out_size) {
    const float* nf   = (const float*)d_in[0];
    const float* rf   = (const float*)d_in[1];
    const float* fw   = (const float*)d_in[2];
    const float* bn0g = (const float*)d_in[3];
    const float* bn0b = (const float*)d_in[4];
    const float* cbng = (const float*)d_in[5];
    const float* cbnb = (const float*)d_in[6];
    const float* bn1g = (const float*)d_in[7];
    const float* bn1b = (const float*)d_in[8];
    const float* fcw  = (const float*)d_in[9];
    const float* fcb  = (const float*)d_in[10];
    const float* bn2g = (const float*)d_in[11];
    const float* bn2b = (const float*)d_in[12];
    const float* eb   = (const float*)d_in[13];
    const int*   sub  = (const int*)d_in[14];
    const int*   rel  = (const int*)d_in[15];
    float* out = (float*)d_out;

    // one-time host-side resources (identical GPU work every call)
    static cudaStream_t s1 = nullptr, s2 = nullptr;
    static cudaEvent_t evRoot = nullptr, evW = nullptr, evNF = nullptr;
    if (!s1) {
        cudaStreamCreateWithFlags(&s1, cudaStreamNonBlocking);
        cudaStreamCreateWithFlags(&s2, cudaStreamNonBlocking);
        cudaEventCreateWithFlags(&evRoot, cudaEventDisableTiming);
        cudaEventCreateWithFlags(&evW, cudaEventDisableTiming);
        cudaEventCreateWithFlags(&evNF, cudaEventDisableTiming);
        cudaFuncSetAttribute(k_out_mma, cudaFuncAttributeMaxDynamicSharedMemorySize, 2 * STAGE_BYTES);
        cudaFuncSetAttribute(k_fc_mma, cudaFuncAttributeMaxDynamicSharedMemorySize, 2 * FC_STG);
    }

    k_init<<<1, 256>>>();
    cudaEventRecord(evRoot, 0);

    // side stream 1: fc weight convert (needed by k_fc_mma)
    cudaStreamWaitEvent(s1, evRoot, 0);
    k_cvt_fcw<<<5000, 256, 0, s1>>>(fcw);
    cudaEventRecord(evW, s1);

    // side stream 2: n_feats convert (needed by k_out_mma)
    cudaStreamWaitEvent(s2, evRoot, 0);
    k_cvt_nf<<<NENTP / 4, 256, 0, s2>>>(nf);
    cudaEventRecord(evNF, s2);

    // main chain
    k_gather<<<BATCH, 512>>>(nf, rf, sub, rel);
    k_conv_stats<<<BATCH, 256>>>(fw, rel, bn0g, bn0b);
    k_conv_fused<<<BATCH, 256>>>(fw, rel, bn0g, bn0b, cbng, bn1g, bn1b);
    cudaStreamWaitEvent(0, evW, 0);
    k_fc_mma<<<dim3(1, 16, KSPLIT), 512, 2 * FC_STG>>>();
    k_fcred<<<BATCH, 256>>>(fcb);
    k_bn1d<<<KPASS, 256>>>(bn2g, bn2b);
    cudaStreamWaitEvent(0, evNF, 0);
    k_out_mma<<<dim3(16, NTILES), 256, 2 * STAGE_BYTES>>>(eb, out);
}

// round 15
// speedup vs baseline: 1.6908x; 1.0003x over previous
#include <cuda_runtime.h>
#include <cuda_fp16.h>
#include <math.h>
#include <stdint.h>

#define BATCH   2048
#define DIM     200
#define OCH     64
#define NPIX    400          // 20x20
#define FLATK   25600        // 64*400
#define NENT    50000
#define EPSF    1e-5f

#define KPASS   256          // padded K storage (200 -> 256)
#define NTILE   128
#define NTILES  391
#define NENTP   (NTILES*NTILE)   // 50048
#define KSPLIT  8
#define KSEG    (FLATK/KSPLIT)   // 3200
#define NPADFC  256
#define FC_CHUNKS 50         // single fp16 pass

// ---------------- scratch ----------------
__device__ float g_X[BATCH * NPIX];
__device__ float g_H[BATCH * DIM];
__device__ float g_sums[2];
__device__ float g_csum[OCH];
__device__ float g_csumsq[OCH];
__device__ __half g_ap[(size_t)BATCH * KPASS];      // scoring A (hi) 1MB
__device__ __half g_bp[(size_t)NENTP * KPASS];      // scoring B (hi) 25.6MB
__device__ __half g_yh[(size_t)BATCH * FLATK];      // fc A 105MB
__device__ __half g_wh[(size_t)DIM * FLATK];        // fc W 10.3MB
__device__ float g_hp[(size_t)KSPLIT * BATCH * NPADFC];

// ---------------- init ----------------
__global__ void k_init() {
    int t = threadIdx.x;
    if (t < 2) g_sums[t] = 0.f;
    if (t < OCH) { g_csum[t] = 0.f; g_csumsq[t] = 0.f; }
}

// ---------------- gather + chequer perm + bn0 stats ----------------
__global__ void k_gather(const float* __restrict__ nf, const float* __restrict__ rf,
                         const int* __restrict__ sub, const int* __restrict__ rel) {
    int b = blockIdx.x;
    int t = threadIdx.x;   // 512
    float v = 0.f;
    if (t < NPIX) {
        int r = t / 20, c = t % 20;
        int idx = r * 10 + (c >> 1);
        int useB = (r + c) & 1;
        v = useB ? rf[rel[b] * DIM + idx]
                 : nf[(size_t)sub[b] * DIM + idx];
        g_X[b * NPIX + t] = v;
    }
    __shared__ float ss[512], sq[512];
    ss[t] = v; sq[t] = v * v;
    __syncthreads();
    for (int s = 256; s > 0; s >>= 1) {
        if (t < s) { ss[t] += ss[t + s]; sq[t] += sq[t + s]; }
        __syncthreads();
    }
    if (t == 0) { atomicAdd(&g_sums[0], ss[0]); atomicAdd(&g_sums[1], sq[0]); }
}

// ---------------- conv prologue ----------------
__device__ __forceinline__ void conv_prologue(int b, int t, float* xs, float* fs,
                                              const float* __restrict__ fw,
                                              const int* __restrict__ rel,
                                              const float* __restrict__ bn0g,
                                              const float* __restrict__ bn0b) {
    float invN = 1.0f / (float)(BATCH * NPIX);
    float m0 = g_sums[0] * invN;
    float v0 = g_sums[1] * invN - m0 * m0;
    float sc0 = bn0g[0] * rsqrtf(v0 + EPSF);
    float sh0 = bn0b[0] - sc0 * m0;
    for (int i = t; i < 484; i += 256) {
        int ph = i / 22, pw = i % 22;
        float val = 0.f;
        if (ph >= 1 && ph <= 20 && pw >= 1 && pw <= 20)
            val = sc0 * g_X[b * NPIX + (ph - 1) * 20 + (pw - 1)] + sh0;
        xs[i] = val;
    }
    int rb = rel[b];
    for (int i = t; i < OCH * 9; i += 256) fs[i] = fw[rb * (OCH * 9) + i];
}

__device__ __forceinline__ float conv_at(const float* xs, const float* f, int pix) {
    int h = pix / 20, w = pix % 20;
    const float* xp = &xs[h * 22 + w];
    return xp[0]  * f[0] + xp[1]  * f[1] + xp[2]  * f[2]
         + xp[22] * f[3] + xp[23] * f[4] + xp[24] * f[5]
         + xp[44] * f[6] + xp[45] * f[7] + xp[46] * f[8];
}

// ---------------- conv pass 1: channel stats ----------------
__global__ void k_conv_stats(const float* __restrict__ fw, const int* __restrict__ rel,
                             const float* __restrict__ bn0g, const float* __restrict__ bn0b) {
    int b = blockIdx.x;
    int t = threadIdx.x;
    __shared__ float xs[22 * 22];
    __shared__ float fs[OCH * 9];
    conv_prologue(b, t, xs, fs, fw, rel, bn0g, bn0b);
    __syncthreads();

    int oc = t >> 2, l4 = t & 3;
    float f[9];
#pragma unroll
    for (int j = 0; j < 9; j++) f[j] = fs[oc * 9 + j];

    float s1 = 0.f, s2 = 0.f;
#pragma unroll 4
    for (int s = 0; s < 100; s++) {
        int pix = l4 + 4 * s;
        float acc = conv_at(xs, f, pix);
        s1 += acc; s2 += acc * acc;
    }
    s1 += __shfl_down_sync(0xffffffffu, s1, 2, 4);
    s1 += __shfl_down_sync(0xffffffffu, s1, 1, 4);
    s2 += __shfl_down_sync(0xffffffffu, s2, 2, 4);
    s2 += __shfl_down_sync(0xffffffffu, s2, 1, 4);
    if (l4 == 0) { atomicAdd(&g_csum[oc], s1); atomicAdd(&g_csumsq[oc], s2); }
}

// ---------------- fc_w -> fp16 (vectorized) ----------------
__global__ void k_cvt_fcw(const float* __restrict__ fw) {
    int i = blockIdx.x * 256 + threadIdx.x;   // 5120000/4 = 1,280,000 float4s
    if (i < 1280000) {
        float4 v = *(const float4*)(fw + (size_t)i * 4);
        __half2* dst = (__half2*)g_wh + (size_t)i * 2;
        dst[0] = __floats2half2_rn(v.x, v.y);
        dst[1] = __floats2half2_rn(v.z, v.w);
    }
}

// ---------------- conv pass 2: BN-compose + BN + relu -> fp16, coalesced ----------------
__global__ void k_conv_fused(const float* __restrict__ fw, const int* __restrict__ rel,
                             const float* __restrict__ bn0g, const float* __restrict__ bn0b,
                             const float* __restrict__ cg, const float* __restrict__ b1g,
                             const float* __restrict__ b1b) {
    int b = blockIdx.x;
    int t = threadIdx.x;   // 256 = 8 warps
    __shared__ float xs[22 * 22];
    __shared__ float fs[OCH * 9];
    __shared__ float sSc[OCH], sSh[OCH];
    conv_prologue(b, t, xs, fs, fw, rel, bn0g, bn0b);
    if (t < OCH) {   // compose the two BN2d (redundant per block; cheap)
        float invN = 1.0f / (float)(BATCH * NPIX);
        float m = g_csum[t] * invN;
        float v = g_csumsq[t] * invN - m * m;
        float t1 = rsqrtf(v + EPSF);
        float var1 = cg[t] * cg[t] * v * t1 * t1;
        float t2 = rsqrtf(var1 + EPSF);
        float sc = b1g[t] * cg[t] * t1 * t2;
        sSc[t] = sc;
        sSh[t] = b1b[t] - sc * m;
    }
    __syncthreads();

    int lane = t & 31, w = t >> 5;   // warp w owns ocs [8w, 8w+8)
#pragma unroll
    for (int j = 0; j < 8; j++) {
        int oc = w * 8 + j;
        float f[9];
#pragma unroll
        for (int q = 0; q < 9; q++) f[q] = fs[oc * 9 + q];
        float sc = sSc[oc], sh = sSh[oc];
        size_t base = ((size_t)b * OCH + oc) * NPIX;
        __half2* dh = (__half2*)(g_yh + base);
        for (int i = lane; i < 200; i += 32) {
            float a0 = conv_at(xs, f, 2 * i);
            float a1 = conv_at(xs, f, 2 * i + 1);
            float z0 = sc * a0 + sh; z0 = z0 > 0.f ? z0 : 0.f;
            float z1 = sc * a1 + sh; z1 = z1 > 0.f ? z1 : 0.f;
            dh[i] = __halves2half2(__float2half_rn(z0), __float2half_rn(z1));
        }
    }
}

// ---------------- n_feats -> fp16 (padded, vectorized: 4 rows/block) ----------------
__global__ void k_cvt_nf(const float* __restrict__ nf) {
    int n = blockIdx.x * 4 + (threadIdx.x >> 6);   // row
    int s = threadIdx.x & 63;                      // 4 k's per slot
    __half2 h0 = __floats2half2_rn(0.f, 0.f), h1 = h0;
    if (n < NENT && 4 * s < DIM) {
        float4 v = *(const float4*)(nf + (size_t)n * DIM + 4 * s);
        h0 = __floats2half2_rn(v.x, v.y);
        h1 = __floats2half2_rn(v.z, v.w);
    }
    __half2* dst = (__half2*)g_bp + (size_t)n * (KPASS / 2) + 2 * s;
    dst[0] = h0;
    dst[1] = h1;
}

// ---------------- mma helpers ----------------
__device__ __forceinline__ uint32_t cvta_smem(const void* p) {
    uint32_t a;
    asm("{ .reg .u64 t; cvta.to.shared.u64 t, %1; cvt.u32.u64 %0, t; }" : "=r"(a) : "l"(p));
    return a;
}
__device__ __forceinline__ void cp16(uint32_t dst, const void* src, uint32_t sz) {
    asm volatile("cp.async.cg.shared.global [%0], [%1], 16, %2;"
                 :: "r"(dst), "l"(src), "r"(sz));
}
__device__ __forceinline__ void cp_commit() {
    asm volatile("cp.async.commit_group;");
}
template <int N>
__device__ __forceinline__ void cp_wait() {
    asm volatile("cp.async.wait_group %0;" :: "n"(N));
}
__device__ __forceinline__ void ldsm_x4(uint32_t& r0, uint32_t& r1, uint32_t& r2, uint32_t& r3,
                                        uint32_t addr) {
    asm volatile("ldmatrix.sync.aligned.m8n8.x4.shared.b16 {%0,%1,%2,%3}, [%4];"
                 : "=r"(r0), "=r"(r1), "=r"(r2), "=r"(r3) : "r"(addr));
}
__device__ __forceinline__ void mma_f16(float& d0, float& d1, float& d2, float& d3,
                                        uint32_t a0, uint32_t a1, uint32_t a2, uint32_t a3,
                                        uint32_t b0, uint32_t b1) {
    asm volatile("mma.sync.aligned.m16n8k16.row.col.f32.f16.f16.f32 "
                 "{%0,%1,%2,%3}, {%4,%5,%6,%7}, {%8,%9}, {%0,%1,%2,%3};"
                 : "+f"(d0), "+f"(d1), "+f"(d2), "+f"(d3)
                 : "r"(a0), "r"(a1), "r"(a2), "r"(a3), "r"(b0), "r"(b1));
}

// ---------------- FC GEMM: CTA 128Mx256N, 512 threads, single pass ----------------
#define FC_ASZ 16384
#define FC_BSZ 32768
#define FC_STG (FC_ASZ + FC_BSZ)    // 48KB per stage

__global__ __launch_bounds__(512, 1) void k_fc_mma() {
    extern __shared__ __align__(1024) unsigned char dsm[];
    int t = threadIdx.x;
    int lane = t & 31, wid = t >> 5;     // 16 warps
    int wm = (wid >> 3) * 64;            // 0 / 64
    int wn = (wid & 7) * 32;             // 0..224
    int m0 = blockIdx.y * 128;
    int ks = blockIdx.z;
    size_t kbase = (size_t)ks * KSEG;

    uint32_t smemBase = cvta_smem(dsm);

    int rowA[2]; uint32_t soA[2]; int segA[2];
#pragma unroll
    for (int r = 0; r < 2; r++) {
        int e = t + 512 * r;
        rowA[r] = e >> 3; segA[r] = e & 7;
        soA[r] = (uint32_t)rowA[r] * 128 + (uint32_t)((segA[r] ^ (rowA[r] & 7)) << 4);
    }
    int rowB[4]; uint32_t soB[4]; int segB[4];
#pragma unroll
    for (int r = 0; r < 4; r++) {
        int e = t + 512 * r;
        rowB[r] = e >> 3; segB[r] = e & 7;
        soB[r] = (uint32_t)rowB[r] * 128 + (uint32_t)((segB[r] ^ (rowB[r] & 7)) << 4);
    }

    int grp = lane >> 3, li = lane & 7;
    int roffA = ((grp & 1) << 3) + li;
    int cgA = grp >> 1;
    int noffB = ((grp >> 1) << 3) + li;
    int cgB = grp & 1;

    float acc[4][4][4];
#pragma unroll
    for (int a = 0; a < 4; a++)
#pragma unroll
        for (int b = 0; b < 4; b++)
#pragma unroll
            for (int c = 0; c < 4; c++) acc[a][b][c] = 0.f;

    auto issue = [&](int idx) {
        size_t koff = kbase + (size_t)idx * 64;
        uint32_t base = smemBase + (uint32_t)(idx & 1) * FC_STG;
#pragma unroll
        for (int r = 0; r < 2; r++) {
            size_t ga = (size_t)(m0 + rowA[r]) * FLATK + koff + segA[r] * 8;
            cp16(base + soA[r], g_yh + ga, 16);
        }
#pragma unroll
        for (int r = 0; r < 4; r++) {
            int nrow = rowB[r];
            int ok = nrow < DIM;
            size_t gb = (size_t)(ok ? nrow : 0) * FLATK + koff + segB[r] * 8;
            cp16(base + FC_ASZ + soB[r], g_wh + gb, ok ? 16u : 0u);
        }
        cp_commit();
    };

    issue(0);
    for (int ch = 0; ch < FC_CHUNKS; ch++) {
        if (ch < FC_CHUNKS - 1) { issue(ch + 1); cp_wait<1>(); }
        else cp_wait<0>();
        __syncthreads();
        uint32_t baseA = smemBase + (uint32_t)(ch & 1) * FC_STG;
        uint32_t baseB = baseA + FC_ASZ;
#pragma unroll
        for (int kf = 0; kf < 4; kf++) {
            uint32_t a[4][4];
#pragma unroll
            for (int mf = 0; mf < 4; mf++) {
                int row = wm + mf * 16 + roffA;
                uint32_t addr = baseA + (uint32_t)row * 128
                              + (uint32_t)(((kf * 2 + cgA) ^ li) << 4);
                ldsm_x4(a[mf][0], a[mf][1], a[mf][2], a[mf][3], addr);
            }
            uint32_t b[4][2];
#pragma unroll
            for (int nf2 = 0; nf2 < 2; nf2++) {
                int row = wn + nf2 * 16 + noffB;
                uint32_t addr = baseB + (uint32_t)row * 128
                              + (uint32_t)(((kf * 2 + cgB) ^ li) << 4);
                ldsm_x4(b[nf2 * 2][0], b[nf2 * 2][1], b[nf2 * 2 + 1][0], b[nf2 * 2 + 1][1], addr);
            }
#pragma unroll
            for (int mf = 0; mf < 4; mf++)
#pragma unroll
                for (int nf = 0; nf < 4; nf++)
                    mma_f16(acc[mf][nf][0], acc[mf][nf][1], acc[mf][nf][2], acc[mf][nf][3],
                            a[mf][0], a[mf][1], a[mf][2], a[mf][3],
                            b[nf][0], b[nf][1]);
        }
        __syncthreads();
    }

    int g = lane >> 2, c = lane & 3;
    float* hp = g_hp + (size_t)ks * BATCH * NPADFC;
#pragma unroll
    for (int mf = 0; mf < 4; mf++) {
#pragma unroll
        for (int nf = 0; nf < 4; nf++) {
            int n = wn + nf * 8 + c * 2;
            int m = m0 + wm + mf * 16 + g;
            float2 v0 = {acc[mf][nf][0], acc[mf][nf][1]};
            *(float2*)(hp + (size_t)m * NPADFC + n) = v0;
            float2 v1 = {acc[mf][nf][2], acc[mf][nf][3]};
            *(float2*)(hp + (size_t)(m + 8) * NPADFC + n) = v1;
        }
    }
}

// ---------------- reduce fc partials + bias ----------------
__global__ void k_fcred(const float* __restrict__ fb) {
    int m = blockIdx.x;
    int t = threadIdx.x;
    if (t >= DIM) return;
    float s = fb[t];
#pragma unroll
    for (int z = 0; z < KSPLIT; z++)
        s += g_hp[((size_t)z * BATCH + m) * NPADFC + t];
    g_H[m * DIM + t] = s;
}

// ---------------- bn1d + relu -> A (hi, padded) ----------------
__global__ void k_bn1d(const float* __restrict__ b2g, const float* __restrict__ b2b) {
    int d = blockIdx.x;     // 0..255
    int t = threadIdx.x;    // 256
    if (d >= DIM) {
        __half z16 = __float2half_rn(0.f);
        for (int i = t; i < BATCH; i += 256)
            g_ap[(size_t)i * KPASS + d] = z16;
        return;
    }
    float vals[8];
    float s1 = 0.f, s2 = 0.f;
#pragma unroll
    for (int i = 0; i < 8; i++) {
        float h = g_H[(t + 256 * i) * DIM + d];
        vals[i] = h; s1 += h; s2 += h * h;
    }
    __shared__ float ss[256], sq[256];
    ss[t] = s1; sq[t] = s2;
    __syncthreads();
    for (int s = 128; s > 0; s >>= 1) {
        if (t < s) { ss[t] += ss[t + s]; sq[t] += sq[t + s]; }
        __syncthreads();
    }
    __shared__ float ssc, ssh;
    if (t == 0) {
        float m = ss[0] / (float)BATCH;
        float v = sq[0] / (float)BATCH - m * m;
        float sc = b2g[d] * rsqrtf(v + EPSF);
        ssc = sc; ssh = b2b[d] - sc * m;
    }
    __syncthreads();
    float sc = ssc, sh = ssh;
#pragma unroll
    for (int i = 0; i < 8; i++) {
        float z = sc * vals[i] + sh;
        z = z > 0.f ? z : 0.f;
        g_ap[(size_t)(t + 256 * i) * KPASS + d] = __float2half_rn(z);
    }
}

// ---------------- scoring GEMM: fp16, effective K=208 ----------------
#define STAGE_BYTES 32768

__global__ __launch_bounds__(256, 2) void k_out_mma(const float* __restrict__ eb,
                                                    float* __restrict__ out) {
    extern __shared__ __align__(1024) unsigned char dsm[];
    int t = threadIdx.x;
    int lane = t & 31, wid = t >> 5;
    int wm = (wid >> 2) * 64;
    int wn = (wid & 3) * 32;
    int m0 = blockIdx.x * 128;
    int n0 = blockIdx.y * NTILE;

    uint32_t smemBase = cvta_smem(dsm);

    int rowL[4]; uint32_t soL[4]; int segL[4];
#pragma unroll
    for (int r = 0; r < 4; r++) {
        int e = t + 256 * r;
        rowL[r] = e >> 3;
        segL[r] = e & 7;
        soL[r] = (uint32_t)rowL[r] * 128 + (uint32_t)((segL[r] ^ (rowL[r] & 7)) << 4);
    }
    const __half* pA = g_ap + (size_t)m0 * KPASS;
    const __half* pB = g_bp + (size_t)n0 * KPASS;

    int grp = lane >> 3, li = lane & 7;
    int roffA = ((grp & 1) << 3) + li;
    int cgA = grp >> 1;
    int noffB = ((grp >> 1) << 3) + li;
    int cgB = grp & 1;

    float acc[4][4][4];
#pragma unroll
    for (int a = 0; a < 4; a++)
#pragma unroll
        for (int b = 0; b < 4; b++)
#pragma unroll
            for (int c = 0; c < 4; c++) acc[a][b][c] = 0.f;

    auto issue = [&](int ch) {
        uint32_t base = smemBase + (uint32_t)(ch & 1) * STAGE_BYTES;
#pragma unroll
        for (int r = 0; r < 4; r++) {
            size_t go = (size_t)rowL[r] * KPASS + ch * 64 + segL[r] * 8;
            cp16(base + soL[r], pA + go, 16);
            cp16(base + 16384 + soL[r], pB + go, 16);
        }
        cp_commit();
    };

    issue(0);
    for (int ch = 0; ch < 4; ch++) {
        if (ch < 3) { issue(ch + 1); cp_wait<1>(); }
        else cp_wait<0>();
        __syncthreads();
        uint32_t baseA = smemBase + (uint32_t)(ch & 1) * STAGE_BYTES;
        uint32_t baseB = baseA + 16384;
        int nkf = (ch == 3) ? 1 : 4;   // K = 3*64 + 16 = 208 >= 200
        for (int kf = 0; kf < nkf; kf++) {
            uint32_t a[4][4];
#pragma unroll
            for (int mf = 0; mf < 4; mf++) {
                int row = wm + mf * 16 + roffA;
                uint32_t addr = baseA + (uint32_t)row * 128
                              + (uint32_t)(((kf * 2 + cgA) ^ li) << 4);
                ldsm_x4(a[mf][0], a[mf][1], a[mf][2], a[mf][3], addr);
            }
            uint32_t b[4][2];
#pragma unroll
            for (int nf2 = 0; nf2 < 2; nf2++) {
                int row = wn + nf2 * 16 + noffB;
                uint32_t addr = baseB + (uint32_t)row * 128
                              + (uint32_t)(((kf * 2 + cgB) ^ li) << 4);
                ldsm_x4(b[nf2 * 2][0], b[nf2 * 2][1], b[nf2 * 2 + 1][0], b[nf2 * 2 + 1][1], addr);
            }
#pragma unroll
            for (int mf = 0; mf < 4; mf++)
#pragma unroll
                for (int nf = 0; nf < 4; nf++)
                    mma_f16(acc[mf][nf][0], acc[mf][nf][1], acc[mf][nf][2], acc[mf][nf][3],
                            a[mf][0], a[mf][1], a[mf][2], a[mf][3],
                            b[nf][0], b[nf][1]);
        }
        __syncthreads();
    }

    int g = lane >> 2, c = lane & 3;
#pragma unroll
    for (int mf = 0; mf < 4; mf++) {
#pragma unroll
        for (int nf = 0; nf < 4; nf++) {
            int n = n0 + wn + nf * 8 + c * 2;
            if (n < NENT) {
                float2 bias = *(const float2*)(eb + n);
                int m = m0 + wm + mf * 16 + g;
                float2 v0 = {acc[mf][nf][0] + bias.x, acc[mf][nf][1] + bias.y};
                *(float2*)(out + (size_t)m * NENT + n) = v0;
                float2 v1 = {acc[mf][nf][2] + bias.x, acc[mf][nf][3] + bias.y};
                *(float2*)(out + (size_t)(m + 8) * NENT + n) = v1;
            }
        }
    }
}

// ---------------- launch ----------------
extern "C" void kernel_launch(void* const* d_in, const int* in_sizes, int n_in,
                              void* d_out, int out_size) {
    const float* nf   = (const float*)d_in[0];
    const float* rf   = (const float*)d_in[1];
    const float* fw   = (const float*)d_in[2];
    const float* bn0g = (const float*)d_in[3];
    const float* bn0b = (const float*)d_in[4];
    const float* cbng = (const float*)d_in[5];
    const float* cbnb = (const float*)d_in[6];
    const float* bn1g = (const float*)d_in[7];
    const float* bn1b = (const float*)d_in[8];
    const float* fcw  = (const float*)d_in[9];
    const float* fcb  = (const float*)d_in[10];
    const float* bn2g = (const float*)d_in[11];
    const float* bn2b = (const float*)d_in[12];
    const float* eb   = (const float*)d_in[13];
    const int*   sub  = (const int*)d_in[14];
    const int*   rel  = (const int*)d_in[15];
    float* out = (float*)d_out;

    // one-time host-side resources (identical GPU work every call)
    static cudaStream_t s1 = nullptr, s2 = nullptr;
    static cudaEvent_t evRoot = nullptr, evW = nullptr, evNF = nullptr;
    if (!s1) {
        cudaStreamCreateWithFlags(&s1, cudaStreamNonBlocking);
        cudaStreamCreateWithFlags(&s2, cudaStreamNonBlocking);
        cudaEventCreateWithFlags(&evRoot, cudaEventDisableTiming);
        cudaEventCreateWithFlags(&evW, cudaEventDisableTiming);
        cudaEventCreateWithFlags(&evNF, cudaEventDisableTiming);
        cudaFuncSetAttribute(k_out_mma, cudaFuncAttributeMaxDynamicSharedMemorySize, 2 * STAGE_BYTES);
        cudaFuncSetAttribute(k_fc_mma, cudaFuncAttributeMaxDynamicSharedMemorySize, 2 * FC_STG);
    }

    k_init<<<1, 256>>>();
    cudaEventRecord(evRoot, 0);

    // side stream 1: fc weight convert (needed by k_fc_mma)
    cudaStreamWaitEvent(s1, evRoot, 0);
    k_cvt_fcw<<<5000, 256, 0, s1>>>(fcw);
    cudaEventRecord(evW, s1);

    // side stream 2: n_feats convert (needed by k_out_mma)
    cudaStreamWaitEvent(s2, evRoot, 0);
    k_cvt_nf<<<NENTP / 4, 256, 0, s2>>>(nf);
    cudaEventRecord(evNF, s2);

    // main chain
    k_gather<<<BATCH, 512>>>(nf, rf, sub, rel);
    k_conv_stats<<<BATCH, 256>>>(fw, rel, bn0g, bn0b);
    k_conv_fused<<<BATCH, 256>>>(fw, rel, bn0g, bn0b, cbng, bn1g, bn1b);
    cudaStreamWaitEvent(0, evW, 0);
    k_fc_mma<<<dim3(1, 16, KSPLIT), 512, 2 * FC_STG>>>();
    k_fcred<<<BATCH, 256>>>(fcb);
    k_bn1d<<<KPASS, 256>>>(bn2g, bn2b);
    cudaStreamWaitEvent(0, evNF, 0);
    k_out_mma<<<dim3(16, NTILES), 256, 2 * STAGE_BYTES>>>(eb, out);
}